// round 9
// baseline (speedup 1.0000x reference)
#include <cuda_runtime.h>
#include <cuda_fp16.h>
#include <mma.h>

using namespace nvcuda;

// ---------------------------------------------------------------------------
// GCNEncoder: 2-layer GCN, N=100000, E=1600000, 1000 node types.
// Round 8: agg1 stages the 256KB h_type table in SHARED MEMORY (two
// column-half blocks of 128KB each) and reads per-edge (type,dis) from a
// packed payload array built in fill_kernel — no dependent gather chain,
// one shfl per edge, LDS instead of L1/L2 gathers.
// ---------------------------------------------------------------------------

#define MAXN 100000
#define MAXE 1600000
#define MAXT 4096
#define SCAN_CHUNK 1024
#define MAXNB ((MAXN + SCAN_CHUNK - 1) / SCAN_CHUNK)

#define A1_THREADS 1024
#define A1_NPB 1376                 // nodes per block (73 blocks per half)
#define A1_SMEM (1024 * 64 * 2)     // 1024 type rows x 64 halves = 128 KB

__device__ int      g_cnt[MAXN];
__device__ int      g_rowptr[MAXN + 1];
__device__ int      g_wptr[MAXN];
__device__ int      g_col[MAXE];
__device__ unsigned g_epay[MAXE];    // (type<<16) | fp16(dis[src])
__device__ int      g_partials[MAXNB];
__device__ float    g_dis[MAXN];
__device__ __half   g_ht[(size_t)MAXT * 128];       // h_type = emb @ W1 (fp16)
__device__ __half   g_a1s[(size_t)MAXN * 128];      // dis * relu(layer1) (fp16)
__device__ __half   g_h2[(size_t)(MAXN + 64) * 64]; // a1s @ W2 (fp16, padded)

// ---------------------------- CSR build -----------------------------------

__global__ void count_kernel(const int* __restrict__ dst, int e, int* __restrict__ cnt) {
    int i = blockIdx.x * blockDim.x + threadIdx.x;
    int i2 = i * 2;
    if (i2 + 1 < e) {
        int2 d = __ldg((const int2*)dst + i);
        atomicAdd(&cnt[d.x], 1);
        atomicAdd(&cnt[d.y], 1);
    } else if (i2 < e) {
        atomicAdd(&cnt[dst[i2]], 1);
    }
}

__global__ __launch_bounds__(256)
void blocksum_kernel(const int* __restrict__ cnt, int* __restrict__ partials, int n) {
    int base = blockIdx.x * SCAN_CHUNK;
    int sum = 0;
    #pragma unroll
    for (int r = 0; r < 4; r++) {
        int i = base + (int)threadIdx.x + r * 256;
        if (i < n) sum += cnt[i];
    }
    #pragma unroll
    for (int off = 16; off > 0; off >>= 1)
        sum += __shfl_down_sync(0xFFFFFFFFu, sum, off);
    __shared__ int ws[8];
    int lane = threadIdx.x & 31, wid = threadIdx.x >> 5;
    if (lane == 0) ws[wid] = sum;
    __syncthreads();
    if (threadIdx.x < 8) {
        int s = ws[threadIdx.x];
        #pragma unroll
        for (int off = 4; off > 0; off >>= 1)
            s += __shfl_down_sync(0xFFu, s, off);
        if (threadIdx.x == 0) partials[blockIdx.x] = s;
    }
}

__global__ __launch_bounds__(256)
void scan_apply_kernel(const int* __restrict__ cnt,
                       const int* __restrict__ partials,
                       int* __restrict__ rowptr,
                       int* __restrict__ wptr,
                       float* __restrict__ dis,
                       int n, int nb) {
    __shared__ int s_offset;
    __shared__ int warp_sums[8];
    int lane = threadIdx.x & 31, wid = threadIdx.x >> 5;

    {
        int p = ((int)threadIdx.x < blockIdx.x && (int)threadIdx.x < nb)
                    ? partials[threadIdx.x] : 0;
        #pragma unroll
        for (int off = 16; off > 0; off >>= 1)
            p += __shfl_down_sync(0xFFFFFFFFu, p, off);
        if (lane == 0) warp_sums[wid] = p;
        __syncthreads();
        if (threadIdx.x < 8) {
            int s = warp_sums[threadIdx.x];
            #pragma unroll
            for (int off = 4; off > 0; off >>= 1)
                s += __shfl_down_sync(0xFFu, s, off);
            if (threadIdx.x == 0) s_offset = s;
        }
        __syncthreads();
    }
    int offset = s_offset;
    __syncthreads();

    int base = blockIdx.x * SCAN_CHUNK;
    int v[4], s_incl[4];
    int run = 0;
    #pragma unroll
    for (int r = 0; r < 4; r++) {
        int i = base + (int)threadIdx.x * 4 + r;
        v[r] = (i < n) ? cnt[i] : 0;
        run += v[r];
        s_incl[r] = run;
    }
    int x = run;
    #pragma unroll
    for (int off = 1; off < 32; off <<= 1) {
        int t = __shfl_up_sync(0xFFFFFFFFu, x, off);
        if (lane >= off) x += t;
    }
    if (lane == 31) warp_sums[wid] = x;
    __syncthreads();
    if (threadIdx.x < 8) {
        int s = warp_sums[threadIdx.x];
        #pragma unroll
        for (int off = 1; off < 8; off <<= 1) {
            int t = __shfl_up_sync(0xFFu, s, off);
            if ((int)threadIdx.x >= off) s += t;
        }
        warp_sums[threadIdx.x] = s;
    }
    __syncthreads();
    int thread_excl = x - run + ((wid > 0) ? warp_sums[wid - 1] : 0);

    #pragma unroll
    for (int r = 0; r < 4; r++) {
        int i = base + (int)threadIdx.x * 4 + r;
        if (i < n) {
            int incl = offset + thread_excl + s_incl[r];
            rowptr[i + 1] = incl;
            wptr[i]       = incl - v[r];
            dis[i]        = rsqrtf((float)(v[r] + 1));
        }
    }
    if (blockIdx.x == 0 && threadIdx.x == 0) rowptr[0] = 0;
}

// fill: scatter src into CSR slots; also pack per-edge payload
// (type[src]<<16 | fp16(dis[src])) so agg1 never chases colx->types/dis.
__global__ void fill_kernel(const int* __restrict__ src, const int* __restrict__ dst,
                            const int* __restrict__ types,
                            const float* __restrict__ dis,
                            int e, int* __restrict__ wptr,
                            int* __restrict__ colx,
                            unsigned* __restrict__ epay) {
    int i = blockIdx.x * blockDim.x + threadIdx.x;
    int i2 = i * 2;
    if (i2 + 1 < e) {
        int2 s = __ldg((const int2*)src + i);
        int2 d = __ldg((const int2*)dst + i);
        unsigned pk0 = ((unsigned)__ldg(&types[s.x]) << 16) |
                       (unsigned)__half_as_ushort(__float2half_rn(__ldg(&dis[s.x])));
        unsigned pk1 = ((unsigned)__ldg(&types[s.y]) << 16) |
                       (unsigned)__half_as_ushort(__float2half_rn(__ldg(&dis[s.y])));
        int p0 = atomicAdd(&wptr[d.x], 1);
        colx[p0] = s.x;
        epay[p0] = pk0;
        int p1 = atomicAdd(&wptr[d.y], 1);
        colx[p1] = s.y;
        epay[p1] = pk1;
    } else if (i2 < e) {
        int s = src[i2];
        unsigned pk = ((unsigned)__ldg(&types[s]) << 16) |
                      (unsigned)__half_as_ushort(__float2half_rn(__ldg(&dis[s])));
        int p = atomicAdd(&wptr[dst[i2]], 1);
        colx[p] = s;
        epay[p] = pk;
    }
}

// ---------------------------- Type GEMM ------------------------------------

__global__ __launch_bounds__(256)
void gemm_type_kernel(const float* __restrict__ A,
                      const float* __restrict__ W,
                      __half* __restrict__ out, int n) {
    __shared__ __align__(16) float As[32][68];
    __shared__ __align__(16) float Bs[32][128];

    int tid = threadIdx.x;
    int tx = tid & 31;
    int ty = tid >> 5;
    int m0 = blockIdx.x * 64;

    float acc[8][4];
    #pragma unroll
    for (int i = 0; i < 8; i++)
        #pragma unroll
        for (int j = 0; j < 4; j++) acc[i][j] = 0.0f;

    for (int kk = 0; kk < 128; kk += 32) {
        #pragma unroll
        for (int r = 0; r < 2; r++) {
            int fi = tid + r * 256;
            int m = fi >> 3;
            int q = fi & 7;
            int row = m0 + m;
            float4 v = make_float4(0.f, 0.f, 0.f, 0.f);
            if (row < n) v = *(const float4*)(A + (size_t)row * 128 + kk + q * 4);
            As[q * 4 + 0][m] = v.x;
            As[q * 4 + 1][m] = v.y;
            As[q * 4 + 2][m] = v.z;
            As[q * 4 + 3][m] = v.w;
        }
        #pragma unroll
        for (int r = 0; r < 4; r++) {
            int fi = tid + r * 256;
            int k  = fi >> 5;
            int c4 = fi & 31;
            *(float4*)&Bs[k][c4 * 4] = *(const float4*)(W + (size_t)(kk + k) * 128 + c4 * 4);
        }
        __syncthreads();
        #pragma unroll
        for (int k = 0; k < 32; k++) {
            float4 a0 = *(const float4*)&As[k][ty * 8];
            float4 a1 = *(const float4*)&As[k][ty * 8 + 4];
            float a[8] = {a0.x, a0.y, a0.z, a0.w, a1.x, a1.y, a1.z, a1.w};
            float4 bv = *(const float4*)&Bs[k][tx * 4];
            float b[4] = {bv.x, bv.y, bv.z, bv.w};
            #pragma unroll
            for (int i = 0; i < 8; i++)
                #pragma unroll
                for (int j = 0; j < 4; j++)
                    acc[i][j] = fmaf(a[i], b[j], acc[i][j]);
        }
        __syncthreads();
    }
    #pragma unroll
    for (int i = 0; i < 8; i++) {
        int row = m0 + ty * 8 + i;
        if (row < n) {
            __half2 h0 = __floats2half2_rn(acc[i][0], acc[i][1]);
            __half2 h1 = __floats2half2_rn(acc[i][2], acc[i][3]);
            uint2 u = make_uint2(*(unsigned*)&h0, *(unsigned*)&h1);
            *(uint2*)(out + (size_t)row * 128 + tx * 4) = u;
        }
    }
}

// ---------------------------- agg1: smem-staged h_type ----------------------
// blockIdx.y = column half (64 cols = 128B/row). Block stages ht's half
// (nt x 64 fp16 <= 128KB) in smem, then one warp per node gathers via LDS.
// Lane covers 2 cols (one half2). Payload gives (type, fp16 dis) per edge.

__global__ __launch_bounds__(A1_THREADS)
void agg1_smem_kernel(const __half* __restrict__ ht,
                      const int* __restrict__ types,
                      const int* __restrict__ rowptr,
                      const unsigned* __restrict__ epay,
                      const float* __restrict__ dis,
                      const float* __restrict__ bias,
                      __half* __restrict__ out, int n, int nt) {
    extern __shared__ __align__(16) __half hs[];   // [nt][64]
    int tid = threadIdx.x;
    int lane = tid & 31;
    int warp = tid >> 5;          // 0..31
    int half = blockIdx.y;        // 0 or 1

    // Stage ht column-half: nt rows x 64 halves = nt*8 uint4.
    int tot = nt * 8;
    for (int i = tid; i < tot; i += A1_THREADS) {
        int row = i >> 3;
        int q   = i & 7;
        uint4 v = *(const uint4*)(ht + (size_t)row * 128 + half * 64 + q * 8);
        *(uint4*)&hs[row * 64 + q * 8] = v;
    }
    __syncthreads();

    float2 bb = *(const float2*)(bias + half * 64 + lane * 2);

    int wend = blockIdx.x * A1_NPB + A1_NPB;
    if (wend > n) wend = n;
    for (int w = blockIdx.x * A1_NPB + warp; w < wend; w += 32) {
        float dd = __ldg(&dis[w]);
        int   td = __ldg(&types[w]);
        float2 acc;
        {
            unsigned u = *(const unsigned*)&hs[td * 64 + lane * 2];
            float2 f = __half22float2(*(__half2*)&u);
            acc.x = dd * f.x;
            acc.y = dd * f.y;
        }

        int j  = __ldg(&rowptr[w]);
        int j1 = __ldg(&rowptr[w + 1]);
        while (j < j1) {
            int m = j1 - j;
            if (m > 32) m = 32;
            unsigned pv = 0;
            if (lane < m) pv = __ldg(&epay[j + lane]);
            int b = 0;
            for (; b + 3 < m; b += 4) {
                unsigned p0 = __shfl_sync(0xFFFFFFFFu, pv, b);
                unsigned p1 = __shfl_sync(0xFFFFFFFFu, pv, b + 1);
                unsigned p2 = __shfl_sync(0xFFFFFFFFu, pv, b + 2);
                unsigned p3 = __shfl_sync(0xFFFFFFFFu, pv, b + 3);
                unsigned u0 = *(const unsigned*)&hs[(p0 >> 16) * 64 + lane * 2];
                unsigned u1 = *(const unsigned*)&hs[(p1 >> 16) * 64 + lane * 2];
                unsigned u2 = *(const unsigned*)&hs[(p2 >> 16) * 64 + lane * 2];
                unsigned u3 = *(const unsigned*)&hs[(p3 >> 16) * 64 + lane * 2];
                float d0 = __half2float(__ushort_as_half((unsigned short)(p0 & 0xFFFF)));
                float d1 = __half2float(__ushort_as_half((unsigned short)(p1 & 0xFFFF)));
                float d2 = __half2float(__ushort_as_half((unsigned short)(p2 & 0xFFFF)));
                float d3 = __half2float(__ushort_as_half((unsigned short)(p3 & 0xFFFF)));
                float2 f0 = __half22float2(*(__half2*)&u0);
                float2 f1 = __half22float2(*(__half2*)&u1);
                float2 f2 = __half22float2(*(__half2*)&u2);
                float2 f3 = __half22float2(*(__half2*)&u3);
                acc.x = fmaf(d0, f0.x, acc.x); acc.y = fmaf(d0, f0.y, acc.y);
                acc.x = fmaf(d1, f1.x, acc.x); acc.y = fmaf(d1, f1.y, acc.y);
                acc.x = fmaf(d2, f2.x, acc.x); acc.y = fmaf(d2, f2.y, acc.y);
                acc.x = fmaf(d3, f3.x, acc.x); acc.y = fmaf(d3, f3.y, acc.y);
            }
            for (; b < m; b++) {
                unsigned p0 = __shfl_sync(0xFFFFFFFFu, pv, b);
                unsigned u0 = *(const unsigned*)&hs[(p0 >> 16) * 64 + lane * 2];
                float d0 = __half2float(__ushort_as_half((unsigned short)(p0 & 0xFFFF)));
                float2 f0 = __half22float2(*(__half2*)&u0);
                acc.x = fmaf(d0, f0.x, acc.x);
                acc.y = fmaf(d0, f0.y, acc.y);
            }
            j += m;
        }

        // r = relu(dd*acc + b); store dd*r (layer-2 source prescale folded in)
        float r0 = dd * fmaxf(fmaf(dd, acc.x, bb.x), 0.0f);
        float r1 = dd * fmaxf(fmaf(dd, acc.y, bb.y), 0.0f);
        __half2 h = __floats2half2_rn(r0, r1);
        *(unsigned*)(out + (size_t)w * 128 + half * 64 + lane * 2) = *(unsigned*)&h;
    }
}

// Fallback (nt > 1024): round-7 global-gather agg1.
__global__ __launch_bounds__(256)
void agg1_fused_kernel(const __half* __restrict__ ht,
                       const int* __restrict__ types,
                       const int* __restrict__ rowptr,
                       const int* __restrict__ colx,
                       const float* __restrict__ dis,
                       const float* __restrict__ bias,
                       __half* __restrict__ out, int n) {
    int w = (int)((blockIdx.x * blockDim.x + threadIdx.x) >> 5);
    int lane = threadIdx.x & 31;
    if (w >= n) return;

    float dd = __ldg(&dis[w]);
    int   td = __ldg(&types[w]);
    float ax, ay, az, aw;
    {
        uint2 u = __ldg((const uint2*)(ht + (size_t)td * 128) + lane);
        float2 f0 = __half22float2(*(__half2*)&u.x);
        float2 f1 = __half22float2(*(__half2*)&u.y);
        ax = dd * f0.x; ay = dd * f0.y; az = dd * f1.x; aw = dd * f1.y;
    }
    int j  = __ldg(&rowptr[w]);
    int j1 = __ldg(&rowptr[w + 1]);
    while (j < j1) {
        int m = j1 - j;
        if (m > 32) m = 32;
        int t = 0;
        float ds = 0.0f;
        if (lane < m) {
            int s = __ldg(&colx[j + lane]);
            t  = __ldg(&types[s]);
            ds = __ldg(&dis[s]);
        }
        for (int b = 0; b < m; b++) {
            int   tA = __shfl_sync(0xFFFFFFFFu, t,  b);
            float dA = __shfl_sync(0xFFFFFFFFu, ds, b);
            uint2 uA = __ldg((const uint2*)(ht + (size_t)tA * 128) + lane);
            float2 a0 = __half22float2(*(__half2*)&uA.x);
            float2 a1 = __half22float2(*(__half2*)&uA.y);
            ax = fmaf(dA, a0.x, ax); ay = fmaf(dA, a0.y, ay);
            az = fmaf(dA, a1.x, az); aw = fmaf(dA, a1.y, aw);
        }
        j += m;
    }
    float4 bb = __ldg((const float4*)bias + lane);
    float r0 = dd * fmaxf(fmaf(dd, ax, bb.x), 0.0f);
    float r1 = dd * fmaxf(fmaf(dd, ay, bb.y), 0.0f);
    float r2 = dd * fmaxf(fmaf(dd, az, bb.z), 0.0f);
    float r3 = dd * fmaxf(fmaf(dd, aw, bb.w), 0.0f);
    __half2 h0 = __floats2half2_rn(r0, r1);
    __half2 h1 = __floats2half2_rn(r2, r3);
    uint2 u = make_uint2(*(unsigned*)&h0, *(unsigned*)&h1);
    ((uint2*)(out + (size_t)w * 128))[lane] = u;
}

// ---------------------------- Layer-2 GEMM (tensor cores) -------------------

__global__ __launch_bounds__(256)
void gemm2_tc_kernel(const __half* __restrict__ A,
                     const float* __restrict__ W32,
                     __half* __restrict__ out, int n) {
    __shared__ __align__(16) __half As[64][136];
    __shared__ __align__(16) __half Ws[128][72];

    int tid = threadIdx.x;
    int wid = tid >> 5;
    int m0 = blockIdx.x * 64;

    #pragma unroll
    for (int r = 0; r < 4; r++) {
        int fi = tid + r * 256;
        int m = fi >> 4;
        int q = fi & 15;
        int row = m0 + m;
        uint4 v = make_uint4(0, 0, 0, 0);
        if (row < n) v = *(const uint4*)(A + (size_t)row * 128 + q * 8);
        *(uint4*)&As[m][q * 8] = v;
    }
    #pragma unroll
    for (int r = 0; r < 8; r++) {
        int fi = tid + r * 256;
        int k = fi >> 4;
        int q = fi & 15;
        float4 v = __ldg((const float4*)(W32 + (size_t)k * 64 + q * 4));
        __half2 h0 = __floats2half2_rn(v.x, v.y);
        __half2 h1 = __floats2half2_rn(v.z, v.w);
        *(uint2*)&Ws[k][q * 4] = make_uint2(*(unsigned*)&h0, *(unsigned*)&h1);
    }
    __syncthreads();

    int wm = wid >> 1;
    int wn = wid & 1;

    wmma::fragment<wmma::accumulator, 16, 16, 16, float> c[2];
    wmma::fill_fragment(c[0], 0.0f);
    wmma::fill_fragment(c[1], 0.0f);

    #pragma unroll
    for (int k = 0; k < 8; k++) {
        wmma::fragment<wmma::matrix_a, 16, 16, 16, __half, wmma::row_major> af;
        wmma::load_matrix_sync(af, &As[wm * 16][k * 16], 136);
        #pragma unroll
        for (int f = 0; f < 2; f++) {
            wmma::fragment<wmma::matrix_b, 16, 16, 16, __half, wmma::row_major> bf;
            wmma::load_matrix_sync(bf, &Ws[k * 16][wn * 32 + f * 16], 72);
            wmma::mma_sync(c[f], af, bf, c[f]);
        }
    }

    #pragma unroll
    for (int f = 0; f < 2; f++) {
        wmma::fragment<wmma::accumulator, 16, 16, 16, __half> ch;
        #pragma unroll
        for (int i = 0; i < ch.num_elements; i++)
            ch.x[i] = __float2half(c[f].x[i]);
        wmma::store_matrix_sync(out + (size_t)(m0 + wm * 16) * 64 + wn * 32 + f * 16,
                                ch, 64, wmma::mem_row_major);
    }
}

// ---------------------------- Layer-2 aggregation ---------------------------

__global__ __launch_bounds__(256)
void agg2_kernel(const __half* __restrict__ h,
                 const int* __restrict__ rowptr,
                 const int* __restrict__ colx,
                 const float* __restrict__ dis,
                 const float* __restrict__ bias,
                 float* __restrict__ out, int n) {
    int w = (int)((blockIdx.x * blockDim.x + threadIdx.x) >> 5);
    int lane = threadIdx.x & 31;
    if (w >= n) return;

    float2 acc;
    {
        unsigned u = __ldg((const unsigned*)(h + (size_t)w * 64) + lane);
        acc = __half22float2(*(__half2*)&u);
    }
    int j  = __ldg(&rowptr[w]);
    int j1 = __ldg(&rowptr[w + 1]);
    while (j < j1) {
        int m = j1 - j;
        if (m > 32) m = 32;
        int s0 = 0;
        if (lane < m) s0 = __ldg(&colx[j + lane]);
        int b = 0;
        for (; b + 3 < m; b += 4) {
            int e0 = __shfl_sync(0xFFFFFFFFu, s0, b);
            int e1 = __shfl_sync(0xFFFFFFFFu, s0, b + 1);
            int e2 = __shfl_sync(0xFFFFFFFFu, s0, b + 2);
            int e3 = __shfl_sync(0xFFFFFFFFu, s0, b + 3);
            unsigned u0 = __ldg((const unsigned*)(h + (size_t)e0 * 64) + lane);
            unsigned u1 = __ldg((const unsigned*)(h + (size_t)e1 * 64) + lane);
            unsigned u2 = __ldg((const unsigned*)(h + (size_t)e2 * 64) + lane);
            unsigned u3 = __ldg((const unsigned*)(h + (size_t)e3 * 64) + lane);
            float2 f0 = __half22float2(*(__half2*)&u0);
            float2 f1 = __half22float2(*(__half2*)&u1);
            float2 f2 = __half22float2(*(__half2*)&u2);
            float2 f3 = __half22float2(*(__half2*)&u3);
            acc.x += (f0.x + f1.x) + (f2.x + f3.x);
            acc.y += (f0.y + f1.y) + (f2.y + f3.y);
        }
        for (; b < m; b++) {
            int eA = __shfl_sync(0xFFFFFFFFu, s0, b);
            unsigned u = __ldg((const unsigned*)(h + (size_t)eA * 64) + lane);
            float2 v = __half22float2(*(__half2*)&u);
            acc.x += v.x;
            acc.y += v.y;
        }
        j += m;
    }
    float sc = __ldg(&dis[w]);
    float2 bb = *(const float2*)(bias + lane * 2);
    *(float2*)(out + (size_t)w * 64 + lane * 2) =
        make_float2(fmaf(sc, acc.x, bb.x), fmaf(sc, acc.y, bb.y));
}

// ---------------------------- Launch ----------------------------------------

extern "C" void kernel_launch(void* const* d_in, const int* in_sizes, int n_in,
                              void* d_out, int out_size) {
    const int*   types = (const int*)d_in[0];
    const int*   ei    = (const int*)d_in[1];
    const float* emb   = (const float*)d_in[2];
    const float* W1    = (const float*)d_in[3];
    const float* b1    = (const float*)d_in[4];
    const float* W2    = (const float*)d_in[5];
    const float* b2    = (const float*)d_in[6];
    float* out = (float*)d_out;

    int n  = in_sizes[0];
    int e  = in_sizes[1] / 2;
    int nt = in_sizes[2] / 128;
    if (n > MAXN) n = MAXN;
    if (e > MAXE) e = MAXE;
    if (nt > MAXT) nt = MAXT;
    const int* src = ei;
    const int* dst = ei + e;

    int *cnt, *rowptr, *wptr, *colx, *partials;
    unsigned *epay;
    float *dis;
    __half *ht, *a1s, *h2;
    cudaGetSymbolAddress((void**)&cnt,      g_cnt);
    cudaGetSymbolAddress((void**)&rowptr,   g_rowptr);
    cudaGetSymbolAddress((void**)&wptr,     g_wptr);
    cudaGetSymbolAddress((void**)&colx,     g_col);
    cudaGetSymbolAddress((void**)&epay,     g_epay);
    cudaGetSymbolAddress((void**)&partials, g_partials);
    cudaGetSymbolAddress((void**)&dis,      g_dis);
    cudaGetSymbolAddress((void**)&ht,       g_ht);
    cudaGetSymbolAddress((void**)&a1s,      g_a1s);
    cudaGetSymbolAddress((void**)&h2,       g_h2);

    int nb    = (n + SCAN_CHUNK - 1) / SCAN_CHUNK;
    int nb_e2 = (e / 2 + 256) / 256;

    gemm_type_kernel<<<(nt + 63) / 64, 256>>>(emb, W1, ht, nt);

    cudaMemsetAsync(cnt, 0, (size_t)n * sizeof(int));
    count_kernel<<<nb_e2, 256>>>(dst, e, cnt);
    blocksum_kernel<<<nb, 256>>>(cnt, partials, n);
    scan_apply_kernel<<<nb, 256>>>(cnt, partials, rowptr, wptr, dis, n, nb);
    fill_kernel<<<nb_e2, 256>>>(src, dst, types, dis, e, wptr, colx, epay);

    if (nt <= 1024) {
        static bool attr_set = false;
        if (!attr_set) {
            cudaFuncSetAttribute(agg1_smem_kernel,
                                 cudaFuncAttributeMaxDynamicSharedMemorySize, A1_SMEM);
            attr_set = true;
        }
        dim3 grid((n + A1_NPB - 1) / A1_NPB, 2);
        agg1_smem_kernel<<<grid, A1_THREADS, A1_SMEM>>>(
            ht, types, rowptr, epay, dis, b1, a1s, n, nt);
    } else {
        agg1_fused_kernel<<<(n + 7) / 8, 256>>>(ht, types, rowptr, colx, dis, b1, a1s, n);
    }

    gemm2_tc_kernel<<<(n + 63) / 64, 256>>>(a1s, W2, h2, n);
    agg2_kernel<<<(n + 7) / 8, 256>>>(h2, rowptr, colx, dis, b2, out, n);
}

// round 10
// speedup vs baseline: 1.1488x; 1.1488x over previous
#include <cuda_runtime.h>
#include <cuda_fp16.h>
#include <mma.h>

using namespace nvcuda;

// ---------------------------------------------------------------------------
// GCNEncoder: 2-layer GCN, N=100000, E=1600000, 1000 node types.
// Round 9: round-7 structure (best) + packed per-edge payload
// epay = (type[src]<<16)|fp16(dis[src]) built in fill_kernel. agg1's inner
// loop: ONE coalesced payload load per 32 edges, ONE shfl per edge, global
// L1 ht gather (x4 unrolled). Removes the two random 4B gathers per edge.
// ---------------------------------------------------------------------------

#define MAXN 100000
#define MAXE 1600000
#define MAXT 4096
#define SCAN_CHUNK 1024
#define MAXNB ((MAXN + SCAN_CHUNK - 1) / SCAN_CHUNK)

__device__ int      g_cnt[MAXN];
__device__ int      g_rowptr[MAXN + 1];
__device__ int      g_wptr[MAXN];
__device__ int      g_col[MAXE];
__device__ unsigned g_epay[MAXE];     // (type<<16) | fp16(dis[src])
__device__ int      g_partials[MAXNB];
__device__ float    g_dis[MAXN];
__device__ __half   g_ht[(size_t)MAXT * 128];       // h_type = emb @ W1 (fp16)
__device__ __half   g_a1s[(size_t)MAXN * 128];      // dis * relu(layer1) (fp16)
__device__ __half   g_h2[(size_t)(MAXN + 64) * 64]; // a1s @ W2 (fp16, padded)

// ---------------------------- CSR build -----------------------------------

__global__ void count_kernel(const int* __restrict__ dst, int e, int* __restrict__ cnt) {
    int i = blockIdx.x * blockDim.x + threadIdx.x;
    int i2 = i * 2;
    if (i2 + 1 < e) {
        int2 d = __ldg((const int2*)dst + i);
        atomicAdd(&cnt[d.x], 1);
        atomicAdd(&cnt[d.y], 1);
    } else if (i2 < e) {
        atomicAdd(&cnt[dst[i2]], 1);
    }
}

__global__ __launch_bounds__(256)
void blocksum_kernel(const int* __restrict__ cnt, int* __restrict__ partials, int n) {
    int base = blockIdx.x * SCAN_CHUNK;
    int sum = 0;
    #pragma unroll
    for (int r = 0; r < 4; r++) {
        int i = base + (int)threadIdx.x + r * 256;
        if (i < n) sum += cnt[i];
    }
    #pragma unroll
    for (int off = 16; off > 0; off >>= 1)
        sum += __shfl_down_sync(0xFFFFFFFFu, sum, off);
    __shared__ int ws[8];
    int lane = threadIdx.x & 31, wid = threadIdx.x >> 5;
    if (lane == 0) ws[wid] = sum;
    __syncthreads();
    if (threadIdx.x < 8) {
        int s = ws[threadIdx.x];
        #pragma unroll
        for (int off = 4; off > 0; off >>= 1)
            s += __shfl_down_sync(0xFFu, s, off);
        if (threadIdx.x == 0) partials[blockIdx.x] = s;
    }
}

__global__ __launch_bounds__(256)
void scan_apply_kernel(const int* __restrict__ cnt,
                       const int* __restrict__ partials,
                       int* __restrict__ rowptr,
                       int* __restrict__ wptr,
                       float* __restrict__ dis,
                       int n, int nb) {
    __shared__ int s_offset;
    __shared__ int warp_sums[8];
    int lane = threadIdx.x & 31, wid = threadIdx.x >> 5;

    {
        int p = ((int)threadIdx.x < blockIdx.x && (int)threadIdx.x < nb)
                    ? partials[threadIdx.x] : 0;
        #pragma unroll
        for (int off = 16; off > 0; off >>= 1)
            p += __shfl_down_sync(0xFFFFFFFFu, p, off);
        if (lane == 0) warp_sums[wid] = p;
        __syncthreads();
        if (threadIdx.x < 8) {
            int s = warp_sums[threadIdx.x];
            #pragma unroll
            for (int off = 4; off > 0; off >>= 1)
                s += __shfl_down_sync(0xFFu, s, off);
            if (threadIdx.x == 0) s_offset = s;
        }
        __syncthreads();
    }
    int offset = s_offset;
    __syncthreads();

    int base = blockIdx.x * SCAN_CHUNK;
    int v[4], s_incl[4];
    int run = 0;
    #pragma unroll
    for (int r = 0; r < 4; r++) {
        int i = base + (int)threadIdx.x * 4 + r;
        v[r] = (i < n) ? cnt[i] : 0;
        run += v[r];
        s_incl[r] = run;
    }
    int x = run;
    #pragma unroll
    for (int off = 1; off < 32; off <<= 1) {
        int t = __shfl_up_sync(0xFFFFFFFFu, x, off);
        if (lane >= off) x += t;
    }
    if (lane == 31) warp_sums[wid] = x;
    __syncthreads();
    if (threadIdx.x < 8) {
        int s = warp_sums[threadIdx.x];
        #pragma unroll
        for (int off = 1; off < 8; off <<= 1) {
            int t = __shfl_up_sync(0xFFu, s, off);
            if ((int)threadIdx.x >= off) s += t;
        }
        warp_sums[threadIdx.x] = s;
    }
    __syncthreads();
    int thread_excl = x - run + ((wid > 0) ? warp_sums[wid - 1] : 0);

    #pragma unroll
    for (int r = 0; r < 4; r++) {
        int i = base + (int)threadIdx.x * 4 + r;
        if (i < n) {
            int incl = offset + thread_excl + s_incl[r];
            rowptr[i + 1] = incl;
            wptr[i]       = incl - v[r];
            dis[i]        = rsqrtf((float)(v[r] + 1));
        }
    }
    if (blockIdx.x == 0 && threadIdx.x == 0) rowptr[0] = 0;
}

// fill: scatter into CSR slots; pack payload (type<<16 | fp16(dis)).
__global__ void fill_kernel(const int* __restrict__ src, const int* __restrict__ dst,
                            const int* __restrict__ types,
                            const float* __restrict__ dis,
                            int e, int* __restrict__ wptr,
                            int* __restrict__ colx,
                            unsigned* __restrict__ epay) {
    int i = blockIdx.x * blockDim.x + threadIdx.x;
    int i2 = i * 2;
    if (i2 + 1 < e) {
        int2 s = __ldg((const int2*)src + i);
        int2 d = __ldg((const int2*)dst + i);
        unsigned pk0 = ((unsigned)__ldg(&types[s.x]) << 16) |
                       (unsigned)__half_as_ushort(__float2half_rn(__ldg(&dis[s.x])));
        unsigned pk1 = ((unsigned)__ldg(&types[s.y]) << 16) |
                       (unsigned)__half_as_ushort(__float2half_rn(__ldg(&dis[s.y])));
        int p0 = atomicAdd(&wptr[d.x], 1);
        colx[p0] = s.x;
        epay[p0] = pk0;
        int p1 = atomicAdd(&wptr[d.y], 1);
        colx[p1] = s.y;
        epay[p1] = pk1;
    } else if (i2 < e) {
        int s = src[i2];
        unsigned pk = ((unsigned)__ldg(&types[s]) << 16) |
                      (unsigned)__half_as_ushort(__float2half_rn(__ldg(&dis[s])));
        int p = atomicAdd(&wptr[dst[i2]], 1);
        colx[p] = s;
        epay[p] = pk;
    }
}

// ---------------------------- Type GEMM ------------------------------------

__global__ __launch_bounds__(256)
void gemm_type_kernel(const float* __restrict__ A,
                      const float* __restrict__ W,
                      __half* __restrict__ out, int n) {
    __shared__ __align__(16) float As[32][68];
    __shared__ __align__(16) float Bs[32][128];

    int tid = threadIdx.x;
    int tx = tid & 31;
    int ty = tid >> 5;
    int m0 = blockIdx.x * 64;

    float acc[8][4];
    #pragma unroll
    for (int i = 0; i < 8; i++)
        #pragma unroll
        for (int j = 0; j < 4; j++) acc[i][j] = 0.0f;

    for (int kk = 0; kk < 128; kk += 32) {
        #pragma unroll
        for (int r = 0; r < 2; r++) {
            int fi = tid + r * 256;
            int m = fi >> 3;
            int q = fi & 7;
            int row = m0 + m;
            float4 v = make_float4(0.f, 0.f, 0.f, 0.f);
            if (row < n) v = *(const float4*)(A + (size_t)row * 128 + kk + q * 4);
            As[q * 4 + 0][m] = v.x;
            As[q * 4 + 1][m] = v.y;
            As[q * 4 + 2][m] = v.z;
            As[q * 4 + 3][m] = v.w;
        }
        #pragma unroll
        for (int r = 0; r < 4; r++) {
            int fi = tid + r * 256;
            int k  = fi >> 5;
            int c4 = fi & 31;
            *(float4*)&Bs[k][c4 * 4] = *(const float4*)(W + (size_t)(kk + k) * 128 + c4 * 4);
        }
        __syncthreads();
        #pragma unroll
        for (int k = 0; k < 32; k++) {
            float4 a0 = *(const float4*)&As[k][ty * 8];
            float4 a1 = *(const float4*)&As[k][ty * 8 + 4];
            float a[8] = {a0.x, a0.y, a0.z, a0.w, a1.x, a1.y, a1.z, a1.w};
            float4 bv = *(const float4*)&Bs[k][tx * 4];
            float b[4] = {bv.x, bv.y, bv.z, bv.w};
            #pragma unroll
            for (int i = 0; i < 8; i++)
                #pragma unroll
                for (int j = 0; j < 4; j++)
                    acc[i][j] = fmaf(a[i], b[j], acc[i][j]);
        }
        __syncthreads();
    }
    #pragma unroll
    for (int i = 0; i < 8; i++) {
        int row = m0 + ty * 8 + i;
        if (row < n) {
            __half2 h0 = __floats2half2_rn(acc[i][0], acc[i][1]);
            __half2 h1 = __floats2half2_rn(acc[i][2], acc[i][3]);
            uint2 u = make_uint2(*(unsigned*)&h0, *(unsigned*)&h1);
            *(uint2*)(out + (size_t)row * 128 + tx * 4) = u;
        }
    }
}

// ---------------------------- Fused layer-1 aggregation ---------------------
// One warp per dst node, 32 lanes x uint2 (4 cols) per ht row. Batch header:
// ONE coalesced epay load. Inner loop x4 unrolled: 1 shfl + 1 LDG per edge.

__global__ __launch_bounds__(256)
void agg1_fused_kernel(const __half* __restrict__ ht,
                       const int* __restrict__ types,
                       const int* __restrict__ rowptr,
                       const unsigned* __restrict__ epay,
                       const float* __restrict__ dis,
                       const float* __restrict__ bias,
                       __half* __restrict__ out, int n) {
    int w = (int)((blockIdx.x * blockDim.x + threadIdx.x) >> 5);
    int lane = threadIdx.x & 31;
    if (w >= n) return;

    float dd = __ldg(&dis[w]);
    int   td = __ldg(&types[w]);
    float ax, ay, az, aw;
    {
        uint2 u = __ldg((const uint2*)(ht + (size_t)td * 128) + lane);
        float2 f0 = __half22float2(*(__half2*)&u.x);
        float2 f1 = __half22float2(*(__half2*)&u.y);
        ax = dd * f0.x; ay = dd * f0.y; az = dd * f1.x; aw = dd * f1.y;
    }

    int j  = __ldg(&rowptr[w]);
    int j1 = __ldg(&rowptr[w + 1]);
    while (j < j1) {
        int m = j1 - j;
        if (m > 32) m = 32;
        unsigned pv = 0;
        if (lane < m) pv = __ldg(&epay[j + lane]);
        int b = 0;
        for (; b + 3 < m; b += 4) {
            unsigned pk0 = __shfl_sync(0xFFFFFFFFu, pv, b);
            unsigned pk1 = __shfl_sync(0xFFFFFFFFu, pv, b + 1);
            unsigned pk2 = __shfl_sync(0xFFFFFFFFu, pv, b + 2);
            unsigned pk3 = __shfl_sync(0xFFFFFFFFu, pv, b + 3);
            uint2 u0 = __ldg((const uint2*)(ht + (size_t)(pk0 >> 16) * 128) + lane);
            uint2 u1 = __ldg((const uint2*)(ht + (size_t)(pk1 >> 16) * 128) + lane);
            uint2 u2 = __ldg((const uint2*)(ht + (size_t)(pk2 >> 16) * 128) + lane);
            uint2 u3 = __ldg((const uint2*)(ht + (size_t)(pk3 >> 16) * 128) + lane);
            float d0 = __half2float(__ushort_as_half((unsigned short)(pk0 & 0xFFFFu)));
            float d1 = __half2float(__ushort_as_half((unsigned short)(pk1 & 0xFFFFu)));
            float d2 = __half2float(__ushort_as_half((unsigned short)(pk2 & 0xFFFFu)));
            float d3 = __half2float(__ushort_as_half((unsigned short)(pk3 & 0xFFFFu)));
            float2 p0 = __half22float2(*(__half2*)&u0.x);
            float2 q0 = __half22float2(*(__half2*)&u0.y);
            float2 p1 = __half22float2(*(__half2*)&u1.x);
            float2 q1 = __half22float2(*(__half2*)&u1.y);
            float2 p2 = __half22float2(*(__half2*)&u2.x);
            float2 q2 = __half22float2(*(__half2*)&u2.y);
            float2 p3 = __half22float2(*(__half2*)&u3.x);
            float2 q3 = __half22float2(*(__half2*)&u3.y);
            ax = fmaf(d0, p0.x, ax); ay = fmaf(d0, p0.y, ay);
            az = fmaf(d0, q0.x, az); aw = fmaf(d0, q0.y, aw);
            ax = fmaf(d1, p1.x, ax); ay = fmaf(d1, p1.y, ay);
            az = fmaf(d1, q1.x, az); aw = fmaf(d1, q1.y, aw);
            ax = fmaf(d2, p2.x, ax); ay = fmaf(d2, p2.y, ay);
            az = fmaf(d2, q2.x, az); aw = fmaf(d2, q2.y, aw);
            ax = fmaf(d3, p3.x, ax); ay = fmaf(d3, p3.y, ay);
            az = fmaf(d3, q3.x, az); aw = fmaf(d3, q3.y, aw);
        }
        for (; b < m; b++) {
            unsigned pk = __shfl_sync(0xFFFFFFFFu, pv, b);
            uint2 uA = __ldg((const uint2*)(ht + (size_t)(pk >> 16) * 128) + lane);
            float dA = __half2float(__ushort_as_half((unsigned short)(pk & 0xFFFFu)));
            float2 a0 = __half22float2(*(__half2*)&uA.x);
            float2 a1 = __half22float2(*(__half2*)&uA.y);
            ax = fmaf(dA, a0.x, ax); ay = fmaf(dA, a0.y, ay);
            az = fmaf(dA, a1.x, az); aw = fmaf(dA, a1.y, aw);
        }
        j += m;
    }

    float4 bb = __ldg((const float4*)bias + lane);
    // r = relu(dd*acc + b); store dd*r (layer-2 source prescale folded in)
    float r0 = dd * fmaxf(fmaf(dd, ax, bb.x), 0.0f);
    float r1 = dd * fmaxf(fmaf(dd, ay, bb.y), 0.0f);
    float r2 = dd * fmaxf(fmaf(dd, az, bb.z), 0.0f);
    float r3 = dd * fmaxf(fmaf(dd, aw, bb.w), 0.0f);
    __half2 h0 = __floats2half2_rn(r0, r1);
    __half2 h1 = __floats2half2_rn(r2, r3);
    uint2 u = make_uint2(*(unsigned*)&h0, *(unsigned*)&h1);
    ((uint2*)(out + (size_t)w * 128))[lane] = u;
}

// ---------------------------- Layer-2 GEMM (tensor cores) -------------------

__global__ __launch_bounds__(256)
void gemm2_tc_kernel(const __half* __restrict__ A,
                     const float* __restrict__ W32,
                     __half* __restrict__ out, int n) {
    __shared__ __align__(16) __half As[64][136];
    __shared__ __align__(16) __half Ws[128][72];

    int tid = threadIdx.x;
    int wid = tid >> 5;
    int m0 = blockIdx.x * 64;

    #pragma unroll
    for (int r = 0; r < 4; r++) {
        int fi = tid + r * 256;
        int m = fi >> 4;
        int q = fi & 15;
        int row = m0 + m;
        uint4 v = make_uint4(0, 0, 0, 0);
        if (row < n) v = *(const uint4*)(A + (size_t)row * 128 + q * 8);
        *(uint4*)&As[m][q * 8] = v;
    }
    #pragma unroll
    for (int r = 0; r < 8; r++) {
        int fi = tid + r * 256;
        int k = fi >> 4;
        int q = fi & 15;
        float4 v = __ldg((const float4*)(W32 + (size_t)k * 64 + q * 4));
        __half2 h0 = __floats2half2_rn(v.x, v.y);
        __half2 h1 = __floats2half2_rn(v.z, v.w);
        *(uint2*)&Ws[k][q * 4] = make_uint2(*(unsigned*)&h0, *(unsigned*)&h1);
    }
    __syncthreads();

    int wm = wid >> 1;
    int wn = wid & 1;

    wmma::fragment<wmma::accumulator, 16, 16, 16, float> c[2];
    wmma::fill_fragment(c[0], 0.0f);
    wmma::fill_fragment(c[1], 0.0f);

    #pragma unroll
    for (int k = 0; k < 8; k++) {
        wmma::fragment<wmma::matrix_a, 16, 16, 16, __half, wmma::row_major> af;
        wmma::load_matrix_sync(af, &As[wm * 16][k * 16], 136);
        #pragma unroll
        for (int f = 0; f < 2; f++) {
            wmma::fragment<wmma::matrix_b, 16, 16, 16, __half, wmma::row_major> bf;
            wmma::load_matrix_sync(bf, &Ws[k * 16][wn * 32 + f * 16], 72);
            wmma::mma_sync(c[f], af, bf, c[f]);
        }
    }

    #pragma unroll
    for (int f = 0; f < 2; f++) {
        wmma::fragment<wmma::accumulator, 16, 16, 16, __half> ch;
        #pragma unroll
        for (int i = 0; i < ch.num_elements; i++)
            ch.x[i] = __float2half(c[f].x[i]);
        wmma::store_matrix_sync(out + (size_t)(m0 + wm * 16) * 64 + wn * 32 + f * 16,
                                ch, 64, wmma::mem_row_major);
    }
}

// ---------------------------- Layer-2 aggregation ---------------------------

__global__ __launch_bounds__(256)
void agg2_kernel(const __half* __restrict__ h,
                 const int* __restrict__ rowptr,
                 const int* __restrict__ colx,
                 const float* __restrict__ dis,
                 const float* __restrict__ bias,
                 float* __restrict__ out, int n) {
    int w = (int)((blockIdx.x * blockDim.x + threadIdx.x) >> 5);
    int lane = threadIdx.x & 31;
    if (w >= n) return;

    float2 acc;
    {
        unsigned u = __ldg((const unsigned*)(h + (size_t)w * 64) + lane);
        acc = __half22float2(*(__half2*)&u);
    }
    int j  = __ldg(&rowptr[w]);
    int j1 = __ldg(&rowptr[w + 1]);
    while (j < j1) {
        int m = j1 - j;
        if (m > 32) m = 32;
        int s0 = 0;
        if (lane < m) s0 = __ldg(&colx[j + lane]);
        int b = 0;
        for (; b + 3 < m; b += 4) {
            int e0 = __shfl_sync(0xFFFFFFFFu, s0, b);
            int e1 = __shfl_sync(0xFFFFFFFFu, s0, b + 1);
            int e2 = __shfl_sync(0xFFFFFFFFu, s0, b + 2);
            int e3 = __shfl_sync(0xFFFFFFFFu, s0, b + 3);
            unsigned u0 = __ldg((const unsigned*)(h + (size_t)e0 * 64) + lane);
            unsigned u1 = __ldg((const unsigned*)(h + (size_t)e1 * 64) + lane);
            unsigned u2 = __ldg((const unsigned*)(h + (size_t)e2 * 64) + lane);
            unsigned u3 = __ldg((const unsigned*)(h + (size_t)e3 * 64) + lane);
            float2 f0 = __half22float2(*(__half2*)&u0);
            float2 f1 = __half22float2(*(__half2*)&u1);
            float2 f2 = __half22float2(*(__half2*)&u2);
            float2 f3 = __half22float2(*(__half2*)&u3);
            acc.x += (f0.x + f1.x) + (f2.x + f3.x);
            acc.y += (f0.y + f1.y) + (f2.y + f3.y);
        }
        for (; b < m; b++) {
            int eA = __shfl_sync(0xFFFFFFFFu, s0, b);
            unsigned u = __ldg((const unsigned*)(h + (size_t)eA * 64) + lane);
            float2 v = __half22float2(*(__half2*)&u);
            acc.x += v.x;
            acc.y += v.y;
        }
        j += m;
    }
    float sc = __ldg(&dis[w]);
    float2 bb = *(const float2*)(bias + lane * 2);
    *(float2*)(out + (size_t)w * 64 + lane * 2) =
        make_float2(fmaf(sc, acc.x, bb.x), fmaf(sc, acc.y, bb.y));
}

// ---------------------------- Launch ----------------------------------------

extern "C" void kernel_launch(void* const* d_in, const int* in_sizes, int n_in,
                              void* d_out, int out_size) {
    const int*   types = (const int*)d_in[0];
    const int*   ei    = (const int*)d_in[1];
    const float* emb   = (const float*)d_in[2];
    const float* W1    = (const float*)d_in[3];
    const float* b1    = (const float*)d_in[4];
    const float* W2    = (const float*)d_in[5];
    const float* b2    = (const float*)d_in[6];
    float* out = (float*)d_out;

    int n  = in_sizes[0];
    int e  = in_sizes[1] / 2;
    int nt = in_sizes[2] / 128;
    if (n > MAXN) n = MAXN;
    if (e > MAXE) e = MAXE;
    if (nt > MAXT) nt = MAXT;
    const int* src = ei;
    const int* dst = ei + e;

    int *cnt, *rowptr, *wptr, *colx, *partials;
    unsigned *epay;
    float *dis;
    __half *ht, *a1s, *h2;
    cudaGetSymbolAddress((void**)&cnt,      g_cnt);
    cudaGetSymbolAddress((void**)&rowptr,   g_rowptr);
    cudaGetSymbolAddress((void**)&wptr,     g_wptr);
    cudaGetSymbolAddress((void**)&colx,     g_col);
    cudaGetSymbolAddress((void**)&epay,     g_epay);
    cudaGetSymbolAddress((void**)&partials, g_partials);
    cudaGetSymbolAddress((void**)&dis,      g_dis);
    cudaGetSymbolAddress((void**)&ht,       g_ht);
    cudaGetSymbolAddress((void**)&a1s,      g_a1s);
    cudaGetSymbolAddress((void**)&h2,       g_h2);

    int nb    = (n + SCAN_CHUNK - 1) / SCAN_CHUNK;
    int nb_e2 = (e / 2 + 256) / 256;

    gemm_type_kernel<<<(nt + 63) / 64, 256>>>(emb, W1, ht, nt);

    cudaMemsetAsync(cnt, 0, (size_t)n * sizeof(int));
    count_kernel<<<nb_e2, 256>>>(dst, e, cnt);
    blocksum_kernel<<<nb, 256>>>(cnt, partials, n);
    scan_apply_kernel<<<nb, 256>>>(cnt, partials, rowptr, wptr, dis, n, nb);
    fill_kernel<<<nb_e2, 256>>>(src, dst, types, dis, e, wptr, colx, epay);

    int agg_blocks = (n + 7) / 8;

    agg1_fused_kernel<<<agg_blocks, 256>>>(ht, types, rowptr, epay, dis, b1, a1s, n);

    gemm2_tc_kernel<<<(n + 63) / 64, 256>>>(a1s, W2, h2, n);
    agg2_kernel<<<agg_blocks, 256>>>(h2, rowptr, colx, dis, b2, out, n);
}

// round 11
// speedup vs baseline: 1.1663x; 1.0152x over previous
#include <cuda_runtime.h>
#include <cuda_fp16.h>
#include <mma.h>

using namespace nvcuda;

// ---------------------------------------------------------------------------
// GCNEncoder: 2-layer GCN, N=100000, E=1600000, 1000 node types.
// Round 10: round-7 structure + (a) interleaved edge record int2{src, pay}
// written with ONE 8B scattered store in fill (pay = type<<16 | fp16(dis));
// agg1 uses pay (1 shfl/edge, no random type/dis gathers), agg2 uses src.
// (b) blocksum fused into scan via publish-then-wait partials.
// ---------------------------------------------------------------------------

#define MAXN 100000
#define MAXE 1600000
#define MAXT 4096
#define SCAN_CHUNK 1024
#define MAXNB ((MAXN + SCAN_CHUNK - 1) / SCAN_CHUNK)

__device__ int    g_cnt[MAXN];
__device__ int    g_rowptr[MAXN + 1];
__device__ int    g_wptr[MAXN];
__device__ int2   g_ecsr[MAXE];       // {src, (type<<16)|fp16(dis[src])}
__device__ int    g_partials[MAXNB];  // published sum+1 (0 = not ready)
__device__ float  g_dis[MAXN];
__device__ __half g_ht[(size_t)MAXT * 128];       // h_type = emb @ W1 (fp16)
__device__ __half g_a1s[(size_t)MAXN * 128];      // dis * relu(layer1) (fp16)
__device__ __half g_h2[(size_t)(MAXN + 64) * 64]; // a1s @ W2 (fp16, padded)

// ---------------------------- CSR build -----------------------------------

__global__ void count_kernel(const int* __restrict__ dst, int e, int* __restrict__ cnt) {
    int i = blockIdx.x * blockDim.x + threadIdx.x;
    int i2 = i * 2;
    if (i2 + 1 < e) {
        int2 d = __ldg((const int2*)dst + i);
        atomicAdd(&cnt[d.x], 1);
        atomicAdd(&cnt[d.y], 1);
    } else if (i2 < e) {
        atomicAdd(&cnt[dst[i2]], 1);
    }
}

// Fused scan: each block computes its 1024-chunk sum, publishes sum+1,
// polls predecessors' partials, then writes rowptr/wptr/dis.
__global__ __launch_bounds__(256)
void scan_fused_kernel(const int* __restrict__ cnt,
                       int* partials,
                       int* __restrict__ rowptr,
                       int* __restrict__ wptr,
                       float* __restrict__ dis,
                       int n, int nb) {
    __shared__ int warp_sums[8];
    __shared__ int s_offset;
    int lane = threadIdx.x & 31, wid = threadIdx.x >> 5;
    int base = blockIdx.x * SCAN_CHUNK;

    // Local 4-elem sequential + block scan of thread totals.
    int v[4], s_incl[4];
    int run = 0;
    #pragma unroll
    for (int r = 0; r < 4; r++) {
        int i = base + (int)threadIdx.x * 4 + r;
        v[r] = (i < n) ? cnt[i] : 0;
        run += v[r];
        s_incl[r] = run;
    }
    int x = run;
    #pragma unroll
    for (int off = 1; off < 32; off <<= 1) {
        int t = __shfl_up_sync(0xFFFFFFFFu, x, off);
        if (lane >= off) x += t;
    }
    if (lane == 31) warp_sums[wid] = x;
    __syncthreads();
    if (threadIdx.x < 8) {
        int s = warp_sums[threadIdx.x];
        #pragma unroll
        for (int off = 1; off < 8; off <<= 1) {
            int t = __shfl_up_sync(0xFFu, s, off);
            if ((int)threadIdx.x >= off) s += t;
        }
        warp_sums[threadIdx.x] = s;
    }
    __syncthreads();
    int block_total = warp_sums[7];
    int thread_excl = x - run + ((wid > 0) ? warp_sums[wid - 1] : 0);

    // Publish own total (sentinel +1), then wait for predecessors.
    if (threadIdx.x == 0)
        atomicExch(&partials[blockIdx.x], block_total + 1);

    {
        int p = 0;
        if ((int)threadIdx.x < blockIdx.x) {
            volatile int* vp = partials;
            int val;
            do { val = vp[threadIdx.x]; } while (val == 0);
            p = val - 1;
        }
        #pragma unroll
        for (int off = 16; off > 0; off >>= 1)
            p += __shfl_down_sync(0xFFFFFFFFu, p, off);
        __syncthreads();   // warp_sums reuse
        if (lane == 0) warp_sums[wid] = p;
        __syncthreads();
        if (threadIdx.x < 8) {
            int s = warp_sums[threadIdx.x];
            #pragma unroll
            for (int off = 4; off > 0; off >>= 1)
                s += __shfl_down_sync(0xFFu, s, off);
            if (threadIdx.x == 0) s_offset = s;
        }
        __syncthreads();
    }
    int offset = s_offset;

    #pragma unroll
    for (int r = 0; r < 4; r++) {
        int i = base + (int)threadIdx.x * 4 + r;
        if (i < n) {
            int incl = offset + thread_excl + s_incl[r];
            rowptr[i + 1] = incl;
            wptr[i]       = incl - v[r];
            dis[i]        = rsqrtf((float)(v[r] + 1));
        }
    }
    if (blockIdx.x == 0 && threadIdx.x == 0) rowptr[0] = 0;
}

// fill: one atomic + ONE 8B scattered store per edge: {src, pay}.
__global__ void fill_kernel(const int* __restrict__ src, const int* __restrict__ dst,
                            const int* __restrict__ types,
                            const float* __restrict__ dis,
                            int e, int* __restrict__ wptr,
                            int2* __restrict__ ecsr) {
    int i = blockIdx.x * blockDim.x + threadIdx.x;
    int i2 = i * 2;
    if (i2 + 1 < e) {
        int2 s = __ldg((const int2*)src + i);
        int2 d = __ldg((const int2*)dst + i);
        int pay0 = (__ldg(&types[s.x]) << 16) |
                   (int)__half_as_ushort(__float2half_rn(__ldg(&dis[s.x])));
        int pay1 = (__ldg(&types[s.y]) << 16) |
                   (int)__half_as_ushort(__float2half_rn(__ldg(&dis[s.y])));
        int p0 = atomicAdd(&wptr[d.x], 1);
        ecsr[p0] = make_int2(s.x, pay0);
        int p1 = atomicAdd(&wptr[d.y], 1);
        ecsr[p1] = make_int2(s.y, pay1);
    } else if (i2 < e) {
        int s = src[i2];
        int pay = (__ldg(&types[s]) << 16) |
                  (int)__half_as_ushort(__float2half_rn(__ldg(&dis[s])));
        int p = atomicAdd(&wptr[dst[i2]], 1);
        ecsr[p] = make_int2(s, pay);
    }
}

// ---------------------------- Type GEMM ------------------------------------

__global__ __launch_bounds__(256)
void gemm_type_kernel(const float* __restrict__ A,
                      const float* __restrict__ W,
                      __half* __restrict__ out, int n) {
    __shared__ __align__(16) float As[32][68];
    __shared__ __align__(16) float Bs[32][128];

    int tid = threadIdx.x;
    int tx = tid & 31;
    int ty = tid >> 5;
    int m0 = blockIdx.x * 64;

    float acc[8][4];
    #pragma unroll
    for (int i = 0; i < 8; i++)
        #pragma unroll
        for (int j = 0; j < 4; j++) acc[i][j] = 0.0f;

    for (int kk = 0; kk < 128; kk += 32) {
        #pragma unroll
        for (int r = 0; r < 2; r++) {
            int fi = tid + r * 256;
            int m = fi >> 3;
            int q = fi & 7;
            int row = m0 + m;
            float4 v = make_float4(0.f, 0.f, 0.f, 0.f);
            if (row < n) v = *(const float4*)(A + (size_t)row * 128 + kk + q * 4);
            As[q * 4 + 0][m] = v.x;
            As[q * 4 + 1][m] = v.y;
            As[q * 4 + 2][m] = v.z;
            As[q * 4 + 3][m] = v.w;
        }
        #pragma unroll
        for (int r = 0; r < 4; r++) {
            int fi = tid + r * 256;
            int k  = fi >> 5;
            int c4 = fi & 31;
            *(float4*)&Bs[k][c4 * 4] = *(const float4*)(W + (size_t)(kk + k) * 128 + c4 * 4);
        }
        __syncthreads();
        #pragma unroll
        for (int k = 0; k < 32; k++) {
            float4 a0 = *(const float4*)&As[k][ty * 8];
            float4 a1 = *(const float4*)&As[k][ty * 8 + 4];
            float a[8] = {a0.x, a0.y, a0.z, a0.w, a1.x, a1.y, a1.z, a1.w};
            float4 bv = *(const float4*)&Bs[k][tx * 4];
            float b[4] = {bv.x, bv.y, bv.z, bv.w};
            #pragma unroll
            for (int i = 0; i < 8; i++)
                #pragma unroll
                for (int j = 0; j < 4; j++)
                    acc[i][j] = fmaf(a[i], b[j], acc[i][j]);
        }
        __syncthreads();
    }
    #pragma unroll
    for (int i = 0; i < 8; i++) {
        int row = m0 + ty * 8 + i;
        if (row < n) {
            __half2 h0 = __floats2half2_rn(acc[i][0], acc[i][1]);
            __half2 h1 = __floats2half2_rn(acc[i][2], acc[i][3]);
            uint2 u = make_uint2(*(unsigned*)&h0, *(unsigned*)&h1);
            *(uint2*)(out + (size_t)row * 128 + tx * 4) = u;
        }
    }
}

// ---------------------------- Fused layer-1 aggregation ---------------------
// One warp per dst node, lane = uint2 (4 cols) of ht row. Batch header: one
// coalesced int2 ecsr load; 1 shfl per edge (payload .y); x4 unroll.

__global__ __launch_bounds__(256)
void agg1_fused_kernel(const __half* __restrict__ ht,
                       const int* __restrict__ types,
                       const int* __restrict__ rowptr,
                       const int2* __restrict__ ecsr,
                       const float* __restrict__ dis,
                       const float* __restrict__ bias,
                       __half* __restrict__ out, int n) {
    int w = (int)((blockIdx.x * blockDim.x + threadIdx.x) >> 5);
    int lane = threadIdx.x & 31;
    if (w >= n) return;

    float dd = __ldg(&dis[w]);
    int   td = __ldg(&types[w]);
    float ax, ay, az, aw;
    {
        uint2 u = __ldg((const uint2*)(ht + (size_t)td * 128) + lane);
        float2 f0 = __half22float2(*(__half2*)&u.x);
        float2 f1 = __half22float2(*(__half2*)&u.y);
        ax = dd * f0.x; ay = dd * f0.y; az = dd * f1.x; aw = dd * f1.y;
    }

    int j  = __ldg(&rowptr[w]);
    int j1 = __ldg(&rowptr[w + 1]);
    while (j < j1) {
        int m = j1 - j;
        if (m > 32) m = 32;
        int pv = 0;
        if (lane < m) pv = __ldg(&ecsr[j + lane].y);
        int b = 0;
        for (; b + 3 < m; b += 4) {
            int pk0 = __shfl_sync(0xFFFFFFFFu, pv, b);
            int pk1 = __shfl_sync(0xFFFFFFFFu, pv, b + 1);
            int pk2 = __shfl_sync(0xFFFFFFFFu, pv, b + 2);
            int pk3 = __shfl_sync(0xFFFFFFFFu, pv, b + 3);
            uint2 u0 = __ldg((const uint2*)(ht + (size_t)((unsigned)pk0 >> 16) * 128) + lane);
            uint2 u1 = __ldg((const uint2*)(ht + (size_t)((unsigned)pk1 >> 16) * 128) + lane);
            uint2 u2 = __ldg((const uint2*)(ht + (size_t)((unsigned)pk2 >> 16) * 128) + lane);
            uint2 u3 = __ldg((const uint2*)(ht + (size_t)((unsigned)pk3 >> 16) * 128) + lane);
            float d0 = __half2float(__ushort_as_half((unsigned short)(pk0 & 0xFFFF)));
            float d1 = __half2float(__ushort_as_half((unsigned short)(pk1 & 0xFFFF)));
            float d2 = __half2float(__ushort_as_half((unsigned short)(pk2 & 0xFFFF)));
            float d3 = __half2float(__ushort_as_half((unsigned short)(pk3 & 0xFFFF)));
            float2 p0 = __half22float2(*(__half2*)&u0.x);
            float2 q0 = __half22float2(*(__half2*)&u0.y);
            float2 p1 = __half22float2(*(__half2*)&u1.x);
            float2 q1 = __half22float2(*(__half2*)&u1.y);
            float2 p2 = __half22float2(*(__half2*)&u2.x);
            float2 q2 = __half22float2(*(__half2*)&u2.y);
            float2 p3 = __half22float2(*(__half2*)&u3.x);
            float2 q3 = __half22float2(*(__half2*)&u3.y);
            ax = fmaf(d0, p0.x, ax); ay = fmaf(d0, p0.y, ay);
            az = fmaf(d0, q0.x, az); aw = fmaf(d0, q0.y, aw);
            ax = fmaf(d1, p1.x, ax); ay = fmaf(d1, p1.y, ay);
            az = fmaf(d1, q1.x, az); aw = fmaf(d1, q1.y, aw);
            ax = fmaf(d2, p2.x, ax); ay = fmaf(d2, p2.y, ay);
            az = fmaf(d2, q2.x, az); aw = fmaf(d2, q2.y, aw);
            ax = fmaf(d3, p3.x, ax); ay = fmaf(d3, p3.y, ay);
            az = fmaf(d3, q3.x, az); aw = fmaf(d3, q3.y, aw);
        }
        for (; b < m; b++) {
            int pk = __shfl_sync(0xFFFFFFFFu, pv, b);
            uint2 uA = __ldg((const uint2*)(ht + (size_t)((unsigned)pk >> 16) * 128) + lane);
            float dA = __half2float(__ushort_as_half((unsigned short)(pk & 0xFFFF)));
            float2 a0 = __half22float2(*(__half2*)&uA.x);
            float2 a1 = __half22float2(*(__half2*)&uA.y);
            ax = fmaf(dA, a0.x, ax); ay = fmaf(dA, a0.y, ay);
            az = fmaf(dA, a1.x, az); aw = fmaf(dA, a1.y, aw);
        }
        j += m;
    }

    float4 bb = __ldg((const float4*)bias + lane);
    // r = relu(dd*acc + b); store dd*r (layer-2 source prescale folded in)
    float r0 = dd * fmaxf(fmaf(dd, ax, bb.x), 0.0f);
    float r1 = dd * fmaxf(fmaf(dd, ay, bb.y), 0.0f);
    float r2 = dd * fmaxf(fmaf(dd, az, bb.z), 0.0f);
    float r3 = dd * fmaxf(fmaf(dd, aw, bb.w), 0.0f);
    __half2 h0 = __floats2half2_rn(r0, r1);
    __half2 h1 = __floats2half2_rn(r2, r3);
    uint2 u = make_uint2(*(unsigned*)&h0, *(unsigned*)&h1);
    ((uint2*)(out + (size_t)w * 128))[lane] = u;
}

// ---------------------------- Layer-2 GEMM (tensor cores) -------------------

__global__ __launch_bounds__(256)
void gemm2_tc_kernel(const __half* __restrict__ A,
                     const float* __restrict__ W32,
                     __half* __restrict__ out, int n) {
    __shared__ __align__(16) __half As[64][136];
    __shared__ __align__(16) __half Ws[128][72];

    int tid = threadIdx.x;
    int wid = tid >> 5;
    int m0 = blockIdx.x * 64;

    #pragma unroll
    for (int r = 0; r < 4; r++) {
        int fi = tid + r * 256;
        int m = fi >> 4;
        int q = fi & 15;
        int row = m0 + m;
        uint4 v = make_uint4(0, 0, 0, 0);
        if (row < n) v = *(const uint4*)(A + (size_t)row * 128 + q * 8);
        *(uint4*)&As[m][q * 8] = v;
    }
    #pragma unroll
    for (int r = 0; r < 8; r++) {
        int fi = tid + r * 256;
        int k = fi >> 4;
        int q = fi & 15;
        float4 v = __ldg((const float4*)(W32 + (size_t)k * 64 + q * 4));
        __half2 h0 = __floats2half2_rn(v.x, v.y);
        __half2 h1 = __floats2half2_rn(v.z, v.w);
        *(uint2*)&Ws[k][q * 4] = make_uint2(*(unsigned*)&h0, *(unsigned*)&h1);
    }
    __syncthreads();

    int wm = wid >> 1;
    int wn = wid & 1;

    wmma::fragment<wmma::accumulator, 16, 16, 16, float> c[2];
    wmma::fill_fragment(c[0], 0.0f);
    wmma::fill_fragment(c[1], 0.0f);

    #pragma unroll
    for (int k = 0; k < 8; k++) {
        wmma::fragment<wmma::matrix_a, 16, 16, 16, __half, wmma::row_major> af;
        wmma::load_matrix_sync(af, &As[wm * 16][k * 16], 136);
        #pragma unroll
        for (int f = 0; f < 2; f++) {
            wmma::fragment<wmma::matrix_b, 16, 16, 16, __half, wmma::row_major> bf;
            wmma::load_matrix_sync(bf, &Ws[k * 16][wn * 32 + f * 16], 72);
            wmma::mma_sync(c[f], af, bf, c[f]);
        }
    }

    #pragma unroll
    for (int f = 0; f < 2; f++) {
        wmma::fragment<wmma::accumulator, 16, 16, 16, __half> ch;
        #pragma unroll
        for (int i = 0; i < ch.num_elements; i++)
            ch.x[i] = __float2half(c[f].x[i]);
        wmma::store_matrix_sync(out + (size_t)(m0 + wm * 16) * 64 + wn * 32 + f * 16,
                                ch, 64, wmma::mem_row_major);
    }
}

// ---------------------------- Layer-2 aggregation ---------------------------

__global__ __launch_bounds__(256)
void agg2_kernel(const __half* __restrict__ h,
                 const int* __restrict__ rowptr,
                 const int2* __restrict__ ecsr,
                 const float* __restrict__ dis,
                 const float* __restrict__ bias,
                 float* __restrict__ out, int n) {
    int w = (int)((blockIdx.x * blockDim.x + threadIdx.x) >> 5);
    int lane = threadIdx.x & 31;
    if (w >= n) return;

    float2 acc;
    {
        unsigned u = __ldg((const unsigned*)(h + (size_t)w * 64) + lane);
        acc = __half22float2(*(__half2*)&u);
    }
    int j  = __ldg(&rowptr[w]);
    int j1 = __ldg(&rowptr[w + 1]);
    while (j < j1) {
        int m = j1 - j;
        if (m > 32) m = 32;
        int s0 = 0;
        if (lane < m) s0 = __ldg(&ecsr[j + lane].x);
        int b = 0;
        for (; b + 3 < m; b += 4) {
            int e0 = __shfl_sync(0xFFFFFFFFu, s0, b);
            int e1 = __shfl_sync(0xFFFFFFFFu, s0, b + 1);
            int e2 = __shfl_sync(0xFFFFFFFFu, s0, b + 2);
            int e3 = __shfl_sync(0xFFFFFFFFu, s0, b + 3);
            unsigned u0 = __ldg((const unsigned*)(h + (size_t)e0 * 64) + lane);
            unsigned u1 = __ldg((const unsigned*)(h + (size_t)e1 * 64) + lane);
            unsigned u2 = __ldg((const unsigned*)(h + (size_t)e2 * 64) + lane);
            unsigned u3 = __ldg((const unsigned*)(h + (size_t)e3 * 64) + lane);
            float2 f0 = __half22float2(*(__half2*)&u0);
            float2 f1 = __half22float2(*(__half2*)&u1);
            float2 f2 = __half22float2(*(__half2*)&u2);
            float2 f3 = __half22float2(*(__half2*)&u3);
            acc.x += (f0.x + f1.x) + (f2.x + f3.x);
            acc.y += (f0.y + f1.y) + (f2.y + f3.y);
        }
        for (; b < m; b++) {
            int eA = __shfl_sync(0xFFFFFFFFu, s0, b);
            unsigned u = __ldg((const unsigned*)(h + (size_t)eA * 64) + lane);
            float2 v = __half22float2(*(__half2*)&u);
            acc.x += v.x;
            acc.y += v.y;
        }
        j += m;
    }
    float sc = __ldg(&dis[w]);
    float2 bb = *(const float2*)(bias + lane * 2);
    *(float2*)(out + (size_t)w * 64 + lane * 2) =
        make_float2(fmaf(sc, acc.x, bb.x), fmaf(sc, acc.y, bb.y));
}

// ---------------------------- Launch ----------------------------------------

extern "C" void kernel_launch(void* const* d_in, const int* in_sizes, int n_in,
                              void* d_out, int out_size) {
    const int*   types = (const int*)d_in[0];
    const int*   ei    = (const int*)d_in[1];
    const float* emb   = (const float*)d_in[2];
    const float* W1    = (const float*)d_in[3];
    const float* b1    = (const float*)d_in[4];
    const float* W2    = (const float*)d_in[5];
    const float* b2    = (const float*)d_in[6];
    float* out = (float*)d_out;

    int n  = in_sizes[0];
    int e  = in_sizes[1] / 2;
    int nt = in_sizes[2] / 128;
    if (n > MAXN) n = MAXN;
    if (e > MAXE) e = MAXE;
    if (nt > MAXT) nt = MAXT;
    const int* src = ei;
    const int* dst = ei + e;

    int *cnt, *rowptr, *wptr, *partials;
    int2 *ecsr;
    float *dis;
    __half *ht, *a1s, *h2;
    cudaGetSymbolAddress((void**)&cnt,      g_cnt);
    cudaGetSymbolAddress((void**)&rowptr,   g_rowptr);
    cudaGetSymbolAddress((void**)&wptr,     g_wptr);
    cudaGetSymbolAddress((void**)&ecsr,     g_ecsr);
    cudaGetSymbolAddress((void**)&partials, g_partials);
    cudaGetSymbolAddress((void**)&dis,      g_dis);
    cudaGetSymbolAddress((void**)&ht,       g_ht);
    cudaGetSymbolAddress((void**)&a1s,      g_a1s);
    cudaGetSymbolAddress((void**)&h2,       g_h2);

    int nb    = (n + SCAN_CHUNK - 1) / SCAN_CHUNK;
    int nb_e2 = (e / 2 + 256) / 256;

    gemm_type_kernel<<<(nt + 63) / 64, 256>>>(emb, W1, ht, nt);

    cudaMemsetAsync(cnt, 0, (size_t)n * sizeof(int));
    cudaMemsetAsync(partials, 0, (size_t)nb * sizeof(int));
    count_kernel<<<nb_e2, 256>>>(dst, e, cnt);
    scan_fused_kernel<<<nb, 256>>>(cnt, partials, rowptr, wptr, dis, n, nb);
    fill_kernel<<<nb_e2, 256>>>(src, dst, types, dis, e, wptr, ecsr);

    int agg_blocks = (n + 7) / 8;

    agg1_fused_kernel<<<agg_blocks, 256>>>(ht, types, rowptr, ecsr, dis, b1, a1s, n);

    gemm2_tc_kernel<<<(n + 63) / 64, 256>>>(a1s, W2, h2, n);
    agg2_kernel<<<agg_blocks, 256>>>(h2, rowptr, ecsr, dis, b2, out, n);
}

// round 12
// speedup vs baseline: 1.2272x; 1.0523x over previous
#include <cuda_runtime.h>
#include <cuda_fp16.h>
#include <mma.h>

using namespace nvcuda;

// ---------------------------------------------------------------------------
// GCNEncoder: 2-layer GCN, N=100000, E=1600000, 1000 node types.
// Round 11: CSR build restructured around measured fill_kernel hotspot
// (29.8us, L2=71%):
//  - count_kernel captures the atomicAdd return as the edge's rank (erank,
//    coalesced store) -> fill needs NO atomics (slot = rowptr[dst]+erank).
//  - scan packs npay[v]=(type<<16)|fp16(dis) coalesced -> fill does ONE
//    random gather (npay) instead of two (types+dis).
//  - partials zeroed inside count_kernel (one less memset launch).
// agg1/agg2/gemms unchanged from round 10.
// ---------------------------------------------------------------------------

#define MAXN 100000
#define MAXE 1600000
#define MAXT 4096
#define SCAN_CHUNK 1024
#define MAXNB ((MAXN + SCAN_CHUNK - 1) / SCAN_CHUNK)

__device__ int    g_cnt[MAXN];
__device__ int    g_rowptr[MAXN + 1];
__device__ int    g_erank[MAXE];      // rank of edge among same-dst edges
__device__ int2   g_ecsr[MAXE];       // {src, (type<<16)|fp16(dis[src])}
__device__ int    g_partials[MAXNB];  // published sum+1 (0 = not ready)
__device__ int    g_npay[MAXN];       // (type<<16)|fp16(dis)
__device__ float  g_dis[MAXN];
__device__ __half g_ht[(size_t)MAXT * 128];       // h_type = emb @ W1 (fp16)
__device__ __half g_a1s[(size_t)MAXN * 128];      // dis * relu(layer1) (fp16)
__device__ __half g_h2[(size_t)(MAXN + 64) * 64]; // a1s @ W2 (fp16, padded)

// ---------------------------- CSR build -----------------------------------

// count: per-edge atomicAdd; SAVE the returned rank (coalesced). Also zeroes
// scan partials (replaces a memset launch).
__global__ void count_kernel(const int* __restrict__ dst, int e,
                             int* __restrict__ cnt,
                             int* __restrict__ erank,
                             int* __restrict__ partials, int nb) {
    int i = blockIdx.x * blockDim.x + threadIdx.x;
    if (i < nb) partials[i] = 0;
    int i2 = i * 2;
    if (i2 + 1 < e) {
        int2 d = __ldg((const int2*)dst + i);
        int r0 = atomicAdd(&cnt[d.x], 1);
        int r1 = atomicAdd(&cnt[d.y], 1);
        *(int2*)(erank + i2) = make_int2(r0, r1);
    } else if (i2 < e) {
        erank[i2] = atomicAdd(&cnt[dst[i2]], 1);
    }
}

// Fused scan: block sum -> publish -> poll predecessors -> write rowptr
// (rowptr[i] = exclusive prefix), dis, npay.
__global__ __launch_bounds__(256)
void scan_fused_kernel(const int* __restrict__ cnt,
                       const int* __restrict__ types,
                       int* partials,
                       int* __restrict__ rowptr,
                       float* __restrict__ dis,
                       int* __restrict__ npay,
                       int n, int nb) {
    __shared__ int warp_sums[8];
    __shared__ int s_offset;
    int lane = threadIdx.x & 31, wid = threadIdx.x >> 5;
    int base = blockIdx.x * SCAN_CHUNK;

    int v[4], s_incl[4];
    int run = 0;
    #pragma unroll
    for (int r = 0; r < 4; r++) {
        int i = base + (int)threadIdx.x * 4 + r;
        v[r] = (i < n) ? cnt[i] : 0;
        run += v[r];
        s_incl[r] = run;
    }
    int x = run;
    #pragma unroll
    for (int off = 1; off < 32; off <<= 1) {
        int t = __shfl_up_sync(0xFFFFFFFFu, x, off);
        if (lane >= off) x += t;
    }
    if (lane == 31) warp_sums[wid] = x;
    __syncthreads();
    if (threadIdx.x < 8) {
        int s = warp_sums[threadIdx.x];
        #pragma unroll
        for (int off = 1; off < 8; off <<= 1) {
            int t = __shfl_up_sync(0xFFu, s, off);
            if ((int)threadIdx.x >= off) s += t;
        }
        warp_sums[threadIdx.x] = s;
    }
    __syncthreads();
    int block_total = warp_sums[7];
    int thread_excl = x - run + ((wid > 0) ? warp_sums[wid - 1] : 0);

    if (threadIdx.x == 0)
        atomicExch(&partials[blockIdx.x], block_total + 1);

    {
        int p = 0;
        if ((int)threadIdx.x < blockIdx.x) {
            volatile int* vp = partials;
            int val;
            do { val = vp[threadIdx.x]; } while (val == 0);
            p = val - 1;
        }
        #pragma unroll
        for (int off = 16; off > 0; off >>= 1)
            p += __shfl_down_sync(0xFFFFFFFFu, p, off);
        __syncthreads();
        if (lane == 0) warp_sums[wid] = p;
        __syncthreads();
        if (threadIdx.x < 8) {
            int s = warp_sums[threadIdx.x];
            #pragma unroll
            for (int off = 4; off > 0; off >>= 1)
                s += __shfl_down_sync(0xFFu, s, off);
            if (threadIdx.x == 0) s_offset = s;
        }
        __syncthreads();
    }
    int offset = s_offset;

    #pragma unroll
    for (int r = 0; r < 4; r++) {
        int i = base + (int)threadIdx.x * 4 + r;
        if (i < n) {
            int incl = offset + thread_excl + s_incl[r];
            rowptr[i + 1] = incl;
            float dv = rsqrtf((float)(v[r] + 1));
            dis[i] = dv;
            npay[i] = (__ldg(&types[i]) << 16) |
                      (int)__half_as_ushort(__float2half_rn(dv));
        }
    }
    if (blockIdx.x == 0 && threadIdx.x == 0) rowptr[0] = 0;
}

// fill: NO atomics. slot = rowptr[dst] (excl prefix) + erank.
// Per edge: coalesced src/dst/erank reads, 2 random gathers, 1 8B store.
__global__ void fill_kernel(const int* __restrict__ src, const int* __restrict__ dst,
                            const int* __restrict__ rowptr,
                            const int* __restrict__ erank,
                            const int* __restrict__ npay,
                            int e, int2* __restrict__ ecsr) {
    int i = blockIdx.x * blockDim.x + threadIdx.x;
    int i2 = i * 2;
    if (i2 + 1 < e) {
        int2 s = __ldg((const int2*)src + i);
        int2 d = __ldg((const int2*)dst + i);
        int2 r = __ldg((const int2*)(erank + i2));
        int p0 = __ldg(&rowptr[d.x]) + r.x;
        int p1 = __ldg(&rowptr[d.y]) + r.y;
        ecsr[p0] = make_int2(s.x, __ldg(&npay[s.x]));
        ecsr[p1] = make_int2(s.y, __ldg(&npay[s.y]));
    } else if (i2 < e) {
        int s = src[i2];
        int p = __ldg(&rowptr[dst[i2]]) + erank[i2];
        ecsr[p] = make_int2(s, __ldg(&npay[s]));
    }
}

// ---------------------------- Type GEMM ------------------------------------

__global__ __launch_bounds__(256)
void gemm_type_kernel(const float* __restrict__ A,
                      const float* __restrict__ W,
                      __half* __restrict__ out, int n) {
    __shared__ __align__(16) float As[32][68];
    __shared__ __align__(16) float Bs[32][128];

    int tid = threadIdx.x;
    int tx = tid & 31;
    int ty = tid >> 5;
    int m0 = blockIdx.x * 64;

    float acc[8][4];
    #pragma unroll
    for (int i = 0; i < 8; i++)
        #pragma unroll
        for (int j = 0; j < 4; j++) acc[i][j] = 0.0f;

    for (int kk = 0; kk < 128; kk += 32) {
        #pragma unroll
        for (int r = 0; r < 2; r++) {
            int fi = tid + r * 256;
            int m = fi >> 3;
            int q = fi & 7;
            int row = m0 + m;
            float4 v = make_float4(0.f, 0.f, 0.f, 0.f);
            if (row < n) v = *(const float4*)(A + (size_t)row * 128 + kk + q * 4);
            As[q * 4 + 0][m] = v.x;
            As[q * 4 + 1][m] = v.y;
            As[q * 4 + 2][m] = v.z;
            As[q * 4 + 3][m] = v.w;
        }
        #pragma unroll
        for (int r = 0; r < 4; r++) {
            int fi = tid + r * 256;
            int k  = fi >> 5;
            int c4 = fi & 31;
            *(float4*)&Bs[k][c4 * 4] = *(const float4*)(W + (size_t)(kk + k) * 128 + c4 * 4);
        }
        __syncthreads();
        #pragma unroll
        for (int k = 0; k < 32; k++) {
            float4 a0 = *(const float4*)&As[k][ty * 8];
            float4 a1 = *(const float4*)&As[k][ty * 8 + 4];
            float a[8] = {a0.x, a0.y, a0.z, a0.w, a1.x, a1.y, a1.z, a1.w};
            float4 bv = *(const float4*)&Bs[k][tx * 4];
            float b[4] = {bv.x, bv.y, bv.z, bv.w};
            #pragma unroll
            for (int i = 0; i < 8; i++)
                #pragma unroll
                for (int j = 0; j < 4; j++)
                    acc[i][j] = fmaf(a[i], b[j], acc[i][j]);
        }
        __syncthreads();
    }
    #pragma unroll
    for (int i = 0; i < 8; i++) {
        int row = m0 + ty * 8 + i;
        if (row < n) {
            __half2 h0 = __floats2half2_rn(acc[i][0], acc[i][1]);
            __half2 h1 = __floats2half2_rn(acc[i][2], acc[i][3]);
            uint2 u = make_uint2(*(unsigned*)&h0, *(unsigned*)&h1);
            *(uint2*)(out + (size_t)row * 128 + tx * 4) = u;
        }
    }
}

// ---------------------------- Fused layer-1 aggregation ---------------------
// One warp per dst node, lane = uint2 (4 cols) of ht row. Batch header: one
// coalesced ecsr.y load; 1 shfl per edge; x4 unroll.

__global__ __launch_bounds__(256)
void agg1_fused_kernel(const __half* __restrict__ ht,
                       const int* __restrict__ types,
                       const int* __restrict__ rowptr,
                       const int2* __restrict__ ecsr,
                       const float* __restrict__ dis,
                       const float* __restrict__ bias,
                       __half* __restrict__ out, int n) {
    int w = (int)((blockIdx.x * blockDim.x + threadIdx.x) >> 5);
    int lane = threadIdx.x & 31;
    if (w >= n) return;

    float dd = __ldg(&dis[w]);
    int   td = __ldg(&types[w]);
    float ax, ay, az, aw;
    {
        uint2 u = __ldg((const uint2*)(ht + (size_t)td * 128) + lane);
        float2 f0 = __half22float2(*(__half2*)&u.x);
        float2 f1 = __half22float2(*(__half2*)&u.y);
        ax = dd * f0.x; ay = dd * f0.y; az = dd * f1.x; aw = dd * f1.y;
    }

    int j  = __ldg(&rowptr[w]);
    int j1 = __ldg(&rowptr[w + 1]);
    while (j < j1) {
        int m = j1 - j;
        if (m > 32) m = 32;
        int pv = 0;
        if (lane < m) pv = __ldg(&ecsr[j + lane].y);
        int b = 0;
        for (; b + 3 < m; b += 4) {
            int pk0 = __shfl_sync(0xFFFFFFFFu, pv, b);
            int pk1 = __shfl_sync(0xFFFFFFFFu, pv, b + 1);
            int pk2 = __shfl_sync(0xFFFFFFFFu, pv, b + 2);
            int pk3 = __shfl_sync(0xFFFFFFFFu, pv, b + 3);
            uint2 u0 = __ldg((const uint2*)(ht + (size_t)((unsigned)pk0 >> 16) * 128) + lane);
            uint2 u1 = __ldg((const uint2*)(ht + (size_t)((unsigned)pk1 >> 16) * 128) + lane);
            uint2 u2 = __ldg((const uint2*)(ht + (size_t)((unsigned)pk2 >> 16) * 128) + lane);
            uint2 u3 = __ldg((const uint2*)(ht + (size_t)((unsigned)pk3 >> 16) * 128) + lane);
            float d0 = __half2float(__ushort_as_half((unsigned short)(pk0 & 0xFFFF)));
            float d1 = __half2float(__ushort_as_half((unsigned short)(pk1 & 0xFFFF)));
            float d2 = __half2float(__ushort_as_half((unsigned short)(pk2 & 0xFFFF)));
            float d3 = __half2float(__ushort_as_half((unsigned short)(pk3 & 0xFFFF)));
            float2 p0 = __half22float2(*(__half2*)&u0.x);
            float2 q0 = __half22float2(*(__half2*)&u0.y);
            float2 p1 = __half22float2(*(__half2*)&u1.x);
            float2 q1 = __half22float2(*(__half2*)&u1.y);
            float2 p2 = __half22float2(*(__half2*)&u2.x);
            float2 q2 = __half22float2(*(__half2*)&u2.y);
            float2 p3 = __half22float2(*(__half2*)&u3.x);
            float2 q3 = __half22float2(*(__half2*)&u3.y);
            ax = fmaf(d0, p0.x, ax); ay = fmaf(d0, p0.y, ay);
            az = fmaf(d0, q0.x, az); aw = fmaf(d0, q0.y, aw);
            ax = fmaf(d1, p1.x, ax); ay = fmaf(d1, p1.y, ay);
            az = fmaf(d1, q1.x, az); aw = fmaf(d1, q1.y, aw);
            ax = fmaf(d2, p2.x, ax); ay = fmaf(d2, p2.y, ay);
            az = fmaf(d2, q2.x, az); aw = fmaf(d2, q2.y, aw);
            ax = fmaf(d3, p3.x, ax); ay = fmaf(d3, p3.y, ay);
            az = fmaf(d3, q3.x, az); aw = fmaf(d3, q3.y, aw);
        }
        for (; b < m; b++) {
            int pk = __shfl_sync(0xFFFFFFFFu, pv, b);
            uint2 uA = __ldg((const uint2*)(ht + (size_t)((unsigned)pk >> 16) * 128) + lane);
            float dA = __half2float(__ushort_as_half((unsigned short)(pk & 0xFFFF)));
            float2 a0 = __half22float2(*(__half2*)&uA.x);
            float2 a1 = __half22float2(*(__half2*)&uA.y);
            ax = fmaf(dA, a0.x, ax); ay = fmaf(dA, a0.y, ay);
            az = fmaf(dA, a1.x, az); aw = fmaf(dA, a1.y, aw);
        }
        j += m;
    }

    float4 bb = __ldg((const float4*)bias + lane);
    float r0 = dd * fmaxf(fmaf(dd, ax, bb.x), 0.0f);
    float r1 = dd * fmaxf(fmaf(dd, ay, bb.y), 0.0f);
    float r2 = dd * fmaxf(fmaf(dd, az, bb.z), 0.0f);
    float r3 = dd * fmaxf(fmaf(dd, aw, bb.w), 0.0f);
    __half2 h0 = __floats2half2_rn(r0, r1);
    __half2 h1 = __floats2half2_rn(r2, r3);
    uint2 u = make_uint2(*(unsigned*)&h0, *(unsigned*)&h1);
    ((uint2*)(out + (size_t)w * 128))[lane] = u;
}

// ---------------------------- Layer-2 GEMM (tensor cores) -------------------

__global__ __launch_bounds__(256)
void gemm2_tc_kernel(const __half* __restrict__ A,
                     const float* __restrict__ W32,
                     __half* __restrict__ out, int n) {
    __shared__ __align__(16) __half As[64][136];
    __shared__ __align__(16) __half Ws[128][72];

    int tid = threadIdx.x;
    int wid = tid >> 5;
    int m0 = blockIdx.x * 64;

    #pragma unroll
    for (int r = 0; r < 4; r++) {
        int fi = tid + r * 256;
        int m = fi >> 4;
        int q = fi & 15;
        int row = m0 + m;
        uint4 v = make_uint4(0, 0, 0, 0);
        if (row < n) v = *(const uint4*)(A + (size_t)row * 128 + q * 8);
        *(uint4*)&As[m][q * 8] = v;
    }
    #pragma unroll
    for (int r = 0; r < 8; r++) {
        int fi = tid + r * 256;
        int k = fi >> 4;
        int q = fi & 15;
        float4 v = __ldg((const float4*)(W32 + (size_t)k * 64 + q * 4));
        __half2 h0 = __floats2half2_rn(v.x, v.y);
        __half2 h1 = __floats2half2_rn(v.z, v.w);
        *(uint2*)&Ws[k][q * 4] = make_uint2(*(unsigned*)&h0, *(unsigned*)&h1);
    }
    __syncthreads();

    int wm = wid >> 1;
    int wn = wid & 1;

    wmma::fragment<wmma::accumulator, 16, 16, 16, float> c[2];
    wmma::fill_fragment(c[0], 0.0f);
    wmma::fill_fragment(c[1], 0.0f);

    #pragma unroll
    for (int k = 0; k < 8; k++) {
        wmma::fragment<wmma::matrix_a, 16, 16, 16, __half, wmma::row_major> af;
        wmma::load_matrix_sync(af, &As[wm * 16][k * 16], 136);
        #pragma unroll
        for (int f = 0; f < 2; f++) {
            wmma::fragment<wmma::matrix_b, 16, 16, 16, __half, wmma::row_major> bf;
            wmma::load_matrix_sync(bf, &Ws[k * 16][wn * 32 + f * 16], 72);
            wmma::mma_sync(c[f], af, bf, c[f]);
        }
    }

    #pragma unroll
    for (int f = 0; f < 2; f++) {
        wmma::fragment<wmma::accumulator, 16, 16, 16, __half> ch;
        #pragma unroll
        for (int i = 0; i < ch.num_elements; i++)
            ch.x[i] = __float2half(c[f].x[i]);
        wmma::store_matrix_sync(out + (size_t)(m0 + wm * 16) * 64 + wn * 32 + f * 16,
                                ch, 64, wmma::mem_row_major);
    }
}

// ---------------------------- Layer-2 aggregation ---------------------------

__global__ __launch_bounds__(256)
void agg2_kernel(const __half* __restrict__ h,
                 const int* __restrict__ rowptr,
                 const int2* __restrict__ ecsr,
                 const float* __restrict__ dis,
                 const float* __restrict__ bias,
                 float* __restrict__ out, int n) {
    int w = (int)((blockIdx.x * blockDim.x + threadIdx.x) >> 5);
    int lane = threadIdx.x & 31;
    if (w >= n) return;

    float2 acc;
    {
        unsigned u = __ldg((const unsigned*)(h + (size_t)w * 64) + lane);
        acc = __half22float2(*(__half2*)&u);
    }
    int j  = __ldg(&rowptr[w]);
    int j1 = __ldg(&rowptr[w + 1]);
    while (j < j1) {
        int m = j1 - j;
        if (m > 32) m = 32;
        int s0 = 0;
        if (lane < m) s0 = __ldg(&ecsr[j + lane].x);
        int b = 0;
        for (; b + 3 < m; b += 4) {
            int e0 = __shfl_sync(0xFFFFFFFFu, s0, b);
            int e1 = __shfl_sync(0xFFFFFFFFu, s0, b + 1);
            int e2 = __shfl_sync(0xFFFFFFFFu, s0, b + 2);
            int e3 = __shfl_sync(0xFFFFFFFFu, s0, b + 3);
            unsigned u0 = __ldg((const unsigned*)(h + (size_t)e0 * 64) + lane);
            unsigned u1 = __ldg((const unsigned*)(h + (size_t)e1 * 64) + lane);
            unsigned u2 = __ldg((const unsigned*)(h + (size_t)e2 * 64) + lane);
            unsigned u3 = __ldg((const unsigned*)(h + (size_t)e3 * 64) + lane);
            float2 f0 = __half22float2(*(__half2*)&u0);
            float2 f1 = __half22float2(*(__half2*)&u1);
            float2 f2 = __half22float2(*(__half2*)&u2);
            float2 f3 = __half22float2(*(__half2*)&u3);
            acc.x += (f0.x + f1.x) + (f2.x + f3.x);
            acc.y += (f0.y + f1.y) + (f2.y + f3.y);
        }
        for (; b < m; b++) {
            int eA = __shfl_sync(0xFFFFFFFFu, s0, b);
            unsigned u = __ldg((const unsigned*)(h + (size_t)eA * 64) + lane);
            float2 v = __half22float2(*(__half2*)&u);
            acc.x += v.x;
            acc.y += v.y;
        }
        j += m;
    }
    float sc = __ldg(&dis[w]);
    float2 bb = *(const float2*)(bias + lane * 2);
    *(float2*)(out + (size_t)w * 64 + lane * 2) =
        make_float2(fmaf(sc, acc.x, bb.x), fmaf(sc, acc.y, bb.y));
}

// ---------------------------- Launch ----------------------------------------

extern "C" void kernel_launch(void* const* d_in, const int* in_sizes, int n_in,
                              void* d_out, int out_size) {
    const int*   types = (const int*)d_in[0];
    const int*   ei    = (const int*)d_in[1];
    const float* emb   = (const float*)d_in[2];
    const float* W1    = (const float*)d_in[3];
    const float* b1    = (const float*)d_in[4];
    const float* W2    = (const float*)d_in[5];
    const float* b2    = (const float*)d_in[6];
    float* out = (float*)d_out;

    int n  = in_sizes[0];
    int e  = in_sizes[1] / 2;
    int nt = in_sizes[2] / 128;
    if (n > MAXN) n = MAXN;
    if (e > MAXE) e = MAXE;
    if (nt > MAXT) nt = MAXT;
    const int* src = ei;
    const int* dst = ei + e;

    int *cnt, *rowptr, *erank, *partials, *npay;
    int2 *ecsr;
    float *dis;
    __half *ht, *a1s, *h2;
    cudaGetSymbolAddress((void**)&cnt,      g_cnt);
    cudaGetSymbolAddress((void**)&rowptr,   g_rowptr);
    cudaGetSymbolAddress((void**)&erank,    g_erank);
    cudaGetSymbolAddress((void**)&ecsr,     g_ecsr);
    cudaGetSymbolAddress((void**)&partials, g_partials);
    cudaGetSymbolAddress((void**)&npay,     g_npay);
    cudaGetSymbolAddress((void**)&dis,      g_dis);
    cudaGetSymbolAddress((void**)&ht,       g_ht);
    cudaGetSymbolAddress((void**)&a1s,      g_a1s);
    cudaGetSymbolAddress((void**)&h2,       g_h2);

    int nb    = (n + SCAN_CHUNK - 1) / SCAN_CHUNK;
    int nb_e2 = (e / 2 + 256) / 256;

    gemm_type_kernel<<<(nt + 63) / 64, 256>>>(emb, W1, ht, nt);

    cudaMemsetAsync(cnt, 0, (size_t)n * sizeof(int));
    count_kernel<<<nb_e2, 256>>>(dst, e, cnt, erank, partials, nb);
    scan_fused_kernel<<<nb, 256>>>(cnt, types, partials, rowptr, dis, npay, n, nb);
    fill_kernel<<<nb_e2, 256>>>(src, dst, rowptr, erank, npay, e, ecsr);

    int agg_blocks = (n + 7) / 8;

    agg1_fused_kernel<<<agg_blocks, 256>>>(ht, types, rowptr, ecsr, dis, b1, a1s, n);

    gemm2_tc_kernel<<<(n + 63) / 64, 256>>>(a1s, W2, h2, n);
    agg2_kernel<<<agg_blocks, 256>>>(h2, rowptr, ecsr, dis, b2, out, n);
}

// round 13
// speedup vs baseline: 1.2460x; 1.0153x over previous
#include <cuda_runtime.h>
#include <cuda_fp16.h>
#include <mma.h>

using namespace nvcuda;

// ---------------------------------------------------------------------------
// GCNEncoder: 2-layer GCN, N=100000, E=1600000, 1000 node types.
// Round 12: fuse gemm_type into count_kernel (heterogeneous grid: edge-count
// blocks + 16 GEMM blocks). Saves a launch AND shifts agg1 into the ncu
// capture slot (4th kernel) so the dominant kernel finally gets profiled.
// agg1/agg2/gemm2/scan/fill byte-identical to round 11 (best, 137.7us).
// ---------------------------------------------------------------------------

#define MAXN 100000
#define MAXE 1600000
#define MAXT 4096
#define SCAN_CHUNK 1024
#define MAXNB ((MAXN + SCAN_CHUNK - 1) / SCAN_CHUNK)

__device__ int    g_cnt[MAXN];
__device__ int    g_rowptr[MAXN + 1];
__device__ int    g_erank[MAXE];      // rank of edge among same-dst edges
__device__ int2   g_ecsr[MAXE];       // {src, (type<<16)|fp16(dis[src])}
__device__ int    g_partials[MAXNB];  // published sum+1 (0 = not ready)
__device__ int    g_npay[MAXN];       // (type<<16)|fp16(dis)
__device__ float  g_dis[MAXN];
__device__ __half g_ht[(size_t)MAXT * 128];       // h_type = emb @ W1 (fp16)
__device__ __half g_a1s[(size_t)MAXN * 128];      // dis * relu(layer1) (fp16)
__device__ __half g_h2[(size_t)(MAXN + 64) * 64]; // a1s @ W2 (fp16, padded)

// -------------------- Fused count + type-GEMM ------------------------------
// Blocks [0, count_blocks): per-edge atomicAdd rank capture (+ partials zero).
// Blocks [count_blocks, count_blocks+gemm_blocks): h_type = emb @ W1 tile.

__global__ __launch_bounds__(256)
void count_gemmtype_kernel(const int* __restrict__ dst, int e,
                           int* __restrict__ cnt,
                           int* __restrict__ erank,
                           int* __restrict__ partials, int nb,
                           const float* __restrict__ emb,
                           const float* __restrict__ W1,
                           __half* __restrict__ ht, int nt,
                           int count_blocks) {
    __shared__ __align__(16) float As[32][68];
    __shared__ __align__(16) float Bs[32][128];

    if ((int)blockIdx.x < count_blocks) {
        int i = blockIdx.x * blockDim.x + threadIdx.x;
        if (i < nb) partials[i] = 0;
        int i2 = i * 2;
        if (i2 + 1 < e) {
            int2 d = __ldg((const int2*)dst + i);
            int r0 = atomicAdd(&cnt[d.x], 1);
            int r1 = atomicAdd(&cnt[d.y], 1);
            *(int2*)(erank + i2) = make_int2(r0, r1);
        } else if (i2 < e) {
            erank[i2] = atomicAdd(&cnt[dst[i2]], 1);
        }
        return;
    }

    // ---- type-GEMM tile: rows [m0, m0+64) of ht = emb @ W1 ----
    int tid = threadIdx.x;
    int tx = tid & 31;
    int ty = tid >> 5;
    int m0 = ((int)blockIdx.x - count_blocks) * 64;

    float acc[8][4];
    #pragma unroll
    for (int i = 0; i < 8; i++)
        #pragma unroll
        for (int j = 0; j < 4; j++) acc[i][j] = 0.0f;

    for (int kk = 0; kk < 128; kk += 32) {
        #pragma unroll
        for (int r = 0; r < 2; r++) {
            int fi = tid + r * 256;
            int m = fi >> 3;
            int q = fi & 7;
            int row = m0 + m;
            float4 v = make_float4(0.f, 0.f, 0.f, 0.f);
            if (row < nt) v = *(const float4*)(emb + (size_t)row * 128 + kk + q * 4);
            As[q * 4 + 0][m] = v.x;
            As[q * 4 + 1][m] = v.y;
            As[q * 4 + 2][m] = v.z;
            As[q * 4 + 3][m] = v.w;
        }
        #pragma unroll
        for (int r = 0; r < 4; r++) {
            int fi = tid + r * 256;
            int k  = fi >> 5;
            int c4 = fi & 31;
            *(float4*)&Bs[k][c4 * 4] = *(const float4*)(W1 + (size_t)(kk + k) * 128 + c4 * 4);
        }
        __syncthreads();
        #pragma unroll
        for (int k = 0; k < 32; k++) {
            float4 a0 = *(const float4*)&As[k][ty * 8];
            float4 a1 = *(const float4*)&As[k][ty * 8 + 4];
            float a[8] = {a0.x, a0.y, a0.z, a0.w, a1.x, a1.y, a1.z, a1.w};
            float4 bv = *(const float4*)&Bs[k][tx * 4];
            float b[4] = {bv.x, bv.y, bv.z, bv.w};
            #pragma unroll
            for (int i = 0; i < 8; i++)
                #pragma unroll
                for (int j = 0; j < 4; j++)
                    acc[i][j] = fmaf(a[i], b[j], acc[i][j]);
        }
        __syncthreads();
    }
    #pragma unroll
    for (int i = 0; i < 8; i++) {
        int row = m0 + ty * 8 + i;
        if (row < nt) {
            __half2 h0 = __floats2half2_rn(acc[i][0], acc[i][1]);
            __half2 h1 = __floats2half2_rn(acc[i][2], acc[i][3]);
            uint2 u = make_uint2(*(unsigned*)&h0, *(unsigned*)&h1);
            *(uint2*)(ht + (size_t)row * 128 + tx * 4) = u;
        }
    }
}

// ---------------------------- Fused scan ------------------------------------
// block sum -> publish -> poll predecessors -> write rowptr, dis, npay.

__global__ __launch_bounds__(256)
void scan_fused_kernel(const int* __restrict__ cnt,
                       const int* __restrict__ types,
                       int* partials,
                       int* __restrict__ rowptr,
                       float* __restrict__ dis,
                       int* __restrict__ npay,
                       int n, int nb) {
    __shared__ int warp_sums[8];
    __shared__ int s_offset;
    int lane = threadIdx.x & 31, wid = threadIdx.x >> 5;
    int base = blockIdx.x * SCAN_CHUNK;

    int v[4], s_incl[4];
    int run = 0;
    #pragma unroll
    for (int r = 0; r < 4; r++) {
        int i = base + (int)threadIdx.x * 4 + r;
        v[r] = (i < n) ? cnt[i] : 0;
        run += v[r];
        s_incl[r] = run;
    }
    int x = run;
    #pragma unroll
    for (int off = 1; off < 32; off <<= 1) {
        int t = __shfl_up_sync(0xFFFFFFFFu, x, off);
        if (lane >= off) x += t;
    }
    if (lane == 31) warp_sums[wid] = x;
    __syncthreads();
    if (threadIdx.x < 8) {
        int s = warp_sums[threadIdx.x];
        #pragma unroll
        for (int off = 1; off < 8; off <<= 1) {
            int t = __shfl_up_sync(0xFFu, s, off);
            if ((int)threadIdx.x >= off) s += t;
        }
        warp_sums[threadIdx.x] = s;
    }
    __syncthreads();
    int block_total = warp_sums[7];
    int thread_excl = x - run + ((wid > 0) ? warp_sums[wid - 1] : 0);

    if (threadIdx.x == 0)
        atomicExch(&partials[blockIdx.x], block_total + 1);

    {
        int p = 0;
        if ((int)threadIdx.x < blockIdx.x) {
            volatile int* vp = partials;
            int val;
            do { val = vp[threadIdx.x]; } while (val == 0);
            p = val - 1;
        }
        #pragma unroll
        for (int off = 16; off > 0; off >>= 1)
            p += __shfl_down_sync(0xFFFFFFFFu, p, off);
        __syncthreads();
        if (lane == 0) warp_sums[wid] = p;
        __syncthreads();
        if (threadIdx.x < 8) {
            int s = warp_sums[threadIdx.x];
            #pragma unroll
            for (int off = 4; off > 0; off >>= 1)
                s += __shfl_down_sync(0xFFu, s, off);
            if (threadIdx.x == 0) s_offset = s;
        }
        __syncthreads();
    }
    int offset = s_offset;

    #pragma unroll
    for (int r = 0; r < 4; r++) {
        int i = base + (int)threadIdx.x * 4 + r;
        if (i < n) {
            int incl = offset + thread_excl + s_incl[r];
            rowptr[i + 1] = incl;
            float dv = rsqrtf((float)(v[r] + 1));
            dis[i] = dv;
            npay[i] = (__ldg(&types[i]) << 16) |
                      (int)__half_as_ushort(__float2half_rn(dv));
        }
    }
    if (blockIdx.x == 0 && threadIdx.x == 0) rowptr[0] = 0;
}

// fill: NO atomics. slot = rowptr[dst] (excl prefix) + erank.
__global__ void fill_kernel(const int* __restrict__ src, const int* __restrict__ dst,
                            const int* __restrict__ rowptr,
                            const int* __restrict__ erank,
                            const int* __restrict__ npay,
                            int e, int2* __restrict__ ecsr) {
    int i = blockIdx.x * blockDim.x + threadIdx.x;
    int i2 = i * 2;
    if (i2 + 1 < e) {
        int2 s = __ldg((const int2*)src + i);
        int2 d = __ldg((const int2*)dst + i);
        int2 r = __ldg((const int2*)(erank + i2));
        int p0 = __ldg(&rowptr[d.x]) + r.x;
        int p1 = __ldg(&rowptr[d.y]) + r.y;
        ecsr[p0] = make_int2(s.x, __ldg(&npay[s.x]));
        ecsr[p1] = make_int2(s.y, __ldg(&npay[s.y]));
    } else if (i2 < e) {
        int s = src[i2];
        int p = __ldg(&rowptr[dst[i2]]) + erank[i2];
        ecsr[p] = make_int2(s, __ldg(&npay[s]));
    }
}

// ---------------------------- Fused layer-1 aggregation ---------------------
// One warp per dst node, lane = uint2 (4 cols) of ht row. Batch header: one
// coalesced ecsr.y load; 1 shfl per edge; x4 unroll. (Identical to R11.)

__global__ __launch_bounds__(256)
void agg1_fused_kernel(const __half* __restrict__ ht,
                       const int* __restrict__ types,
                       const int* __restrict__ rowptr,
                       const int2* __restrict__ ecsr,
                       const float* __restrict__ dis,
                       const float* __restrict__ bias,
                       __half* __restrict__ out, int n) {
    int w = (int)((blockIdx.x * blockDim.x + threadIdx.x) >> 5);
    int lane = threadIdx.x & 31;
    if (w >= n) return;

    float dd = __ldg(&dis[w]);
    int   td = __ldg(&types[w]);
    float ax, ay, az, aw;
    {
        uint2 u = __ldg((const uint2*)(ht + (size_t)td * 128) + lane);
        float2 f0 = __half22float2(*(__half2*)&u.x);
        float2 f1 = __half22float2(*(__half2*)&u.y);
        ax = dd * f0.x; ay = dd * f0.y; az = dd * f1.x; aw = dd * f1.y;
    }

    int j  = __ldg(&rowptr[w]);
    int j1 = __ldg(&rowptr[w + 1]);
    while (j < j1) {
        int m = j1 - j;
        if (m > 32) m = 32;
        int pv = 0;
        if (lane < m) pv = __ldg(&ecsr[j + lane].y);
        int b = 0;
        for (; b + 3 < m; b += 4) {
            int pk0 = __shfl_sync(0xFFFFFFFFu, pv, b);
            int pk1 = __shfl_sync(0xFFFFFFFFu, pv, b + 1);
            int pk2 = __shfl_sync(0xFFFFFFFFu, pv, b + 2);
            int pk3 = __shfl_sync(0xFFFFFFFFu, pv, b + 3);
            uint2 u0 = __ldg((const uint2*)(ht + (size_t)((unsigned)pk0 >> 16) * 128) + lane);
            uint2 u1 = __ldg((const uint2*)(ht + (size_t)((unsigned)pk1 >> 16) * 128) + lane);
            uint2 u2 = __ldg((const uint2*)(ht + (size_t)((unsigned)pk2 >> 16) * 128) + lane);
            uint2 u3 = __ldg((const uint2*)(ht + (size_t)((unsigned)pk3 >> 16) * 128) + lane);
            float d0 = __half2float(__ushort_as_half((unsigned short)(pk0 & 0xFFFF)));
            float d1 = __half2float(__ushort_as_half((unsigned short)(pk1 & 0xFFFF)));
            float d2 = __half2float(__ushort_as_half((unsigned short)(pk2 & 0xFFFF)));
            float d3 = __half2float(__ushort_as_half((unsigned short)(pk3 & 0xFFFF)));
            float2 p0 = __half22float2(*(__half2*)&u0.x);
            float2 q0 = __half22float2(*(__half2*)&u0.y);
            float2 p1 = __half22float2(*(__half2*)&u1.x);
            float2 q1 = __half22float2(*(__half2*)&u1.y);
            float2 p2 = __half22float2(*(__half2*)&u2.x);
            float2 q2 = __half22float2(*(__half2*)&u2.y);
            float2 p3 = __half22float2(*(__half2*)&u3.x);
            float2 q3 = __half22float2(*(__half2*)&u3.y);
            ax = fmaf(d0, p0.x, ax); ay = fmaf(d0, p0.y, ay);
            az = fmaf(d0, q0.x, az); aw = fmaf(d0, q0.y, aw);
            ax = fmaf(d1, p1.x, ax); ay = fmaf(d1, p1.y, ay);
            az = fmaf(d1, q1.x, az); aw = fmaf(d1, q1.y, aw);
            ax = fmaf(d2, p2.x, ax); ay = fmaf(d2, p2.y, ay);
            az = fmaf(d2, q2.x, az); aw = fmaf(d2, q2.y, aw);
            ax = fmaf(d3, p3.x, ax); ay = fmaf(d3, p3.y, ay);
            az = fmaf(d3, q3.x, az); aw = fmaf(d3, q3.y, aw);
        }
        for (; b < m; b++) {
            int pk = __shfl_sync(0xFFFFFFFFu, pv, b);
            uint2 uA = __ldg((const uint2*)(ht + (size_t)((unsigned)pk >> 16) * 128) + lane);
            float dA = __half2float(__ushort_as_half((unsigned short)(pk & 0xFFFF)));
            float2 a0 = __half22float2(*(__half2*)&uA.x);
            float2 a1 = __half22float2(*(__half2*)&uA.y);
            ax = fmaf(dA, a0.x, ax); ay = fmaf(dA, a0.y, ay);
            az = fmaf(dA, a1.x, az); aw = fmaf(dA, a1.y, aw);
        }
        j += m;
    }

    float4 bb = __ldg((const float4*)bias + lane);
    float r0 = dd * fmaxf(fmaf(dd, ax, bb.x), 0.0f);
    float r1 = dd * fmaxf(fmaf(dd, ay, bb.y), 0.0f);
    float r2 = dd * fmaxf(fmaf(dd, az, bb.z), 0.0f);
    float r3 = dd * fmaxf(fmaf(dd, aw, bb.w), 0.0f);
    __half2 h0 = __floats2half2_rn(r0, r1);
    __half2 h1 = __floats2half2_rn(r2, r3);
    uint2 u = make_uint2(*(unsigned*)&h0, *(unsigned*)&h1);
    ((uint2*)(out + (size_t)w * 128))[lane] = u;
}

// ---------------------------- Layer-2 GEMM (tensor cores) -------------------

__global__ __launch_bounds__(256)
void gemm2_tc_kernel(const __half* __restrict__ A,
                     const float* __restrict__ W32,
                     __half* __restrict__ out, int n) {
    __shared__ __align__(16) __half As[64][136];
    __shared__ __align__(16) __half Ws[128][72];

    int tid = threadIdx.x;
    int wid = tid >> 5;
    int m0 = blockIdx.x * 64;

    #pragma unroll
    for (int r = 0; r < 4; r++) {
        int fi = tid + r * 256;
        int m = fi >> 4;
        int q = fi & 15;
        int row = m0 + m;
        uint4 v = make_uint4(0, 0, 0, 0);
        if (row < n) v = *(const uint4*)(A + (size_t)row * 128 + q * 8);
        *(uint4*)&As[m][q * 8] = v;
    }
    #pragma unroll
    for (int r = 0; r < 8; r++) {
        int fi = tid + r * 256;
        int k = fi >> 4;
        int q = fi & 15;
        float4 v = __ldg((const float4*)(W32 + (size_t)k * 64 + q * 4));
        __half2 h0 = __floats2half2_rn(v.x, v.y);
        __half2 h1 = __floats2half2_rn(v.z, v.w);
        *(uint2*)&Ws[k][q * 4] = make_uint2(*(unsigned*)&h0, *(unsigned*)&h1);
    }
    __syncthreads();

    int wm = wid >> 1;
    int wn = wid & 1;

    wmma::fragment<wmma::accumulator, 16, 16, 16, float> c[2];
    wmma::fill_fragment(c[0], 0.0f);
    wmma::fill_fragment(c[1], 0.0f);

    #pragma unroll
    for (int k = 0; k < 8; k++) {
        wmma::fragment<wmma::matrix_a, 16, 16, 16, __half, wmma::row_major> af;
        wmma::load_matrix_sync(af, &As[wm * 16][k * 16], 136);
        #pragma unroll
        for (int f = 0; f < 2; f++) {
            wmma::fragment<wmma::matrix_b, 16, 16, 16, __half, wmma::row_major> bf;
            wmma::load_matrix_sync(bf, &Ws[k * 16][wn * 32 + f * 16], 72);
            wmma::mma_sync(c[f], af, bf, c[f]);
        }
    }

    #pragma unroll
    for (int f = 0; f < 2; f++) {
        wmma::fragment<wmma::accumulator, 16, 16, 16, __half> ch;
        #pragma unroll
        for (int i = 0; i < ch.num_elements; i++)
            ch.x[i] = __float2half(c[f].x[i]);
        wmma::store_matrix_sync(out + (size_t)(m0 + wm * 16) * 64 + wn * 32 + f * 16,
                                ch, 64, wmma::mem_row_major);
    }
}

// ---------------------------- Layer-2 aggregation ---------------------------

__global__ __launch_bounds__(256)
void agg2_kernel(const __half* __restrict__ h,
                 const int* __restrict__ rowptr,
                 const int2* __restrict__ ecsr,
                 const float* __restrict__ dis,
                 const float* __restrict__ bias,
                 float* __restrict__ out, int n) {
    int w = (int)((blockIdx.x * blockDim.x + threadIdx.x) >> 5);
    int lane = threadIdx.x & 31;
    if (w >= n) return;

    float2 acc;
    {
        unsigned u = __ldg((const unsigned*)(h + (size_t)w * 64) + lane);
        acc = __half22float2(*(__half2*)&u);
    }
    int j  = __ldg(&rowptr[w]);
    int j1 = __ldg(&rowptr[w + 1]);
    while (j < j1) {
        int m = j1 - j;
        if (m > 32) m = 32;
        int s0 = 0;
        if (lane < m) s0 = __ldg(&ecsr[j + lane].x);
        int b = 0;
        for (; b + 3 < m; b += 4) {
            int e0 = __shfl_sync(0xFFFFFFFFu, s0, b);
            int e1 = __shfl_sync(0xFFFFFFFFu, s0, b + 1);
            int e2 = __shfl_sync(0xFFFFFFFFu, s0, b + 2);
            int e3 = __shfl_sync(0xFFFFFFFFu, s0, b + 3);
            unsigned u0 = __ldg((const unsigned*)(h + (size_t)e0 * 64) + lane);
            unsigned u1 = __ldg((const unsigned*)(h + (size_t)e1 * 64) + lane);
            unsigned u2 = __ldg((const unsigned*)(h + (size_t)e2 * 64) + lane);
            unsigned u3 = __ldg((const unsigned*)(h + (size_t)e3 * 64) + lane);
            float2 f0 = __half22float2(*(__half2*)&u0);
            float2 f1 = __half22float2(*(__half2*)&u1);
            float2 f2 = __half22float2(*(__half2*)&u2);
            float2 f3 = __half22float2(*(__half2*)&u3);
            acc.x += (f0.x + f1.x) + (f2.x + f3.x);
            acc.y += (f0.y + f1.y) + (f2.y + f3.y);
        }
        for (; b < m; b++) {
            int eA = __shfl_sync(0xFFFFFFFFu, s0, b);
            unsigned u = __ldg((const unsigned*)(h + (size_t)eA * 64) + lane);
            float2 v = __half22float2(*(__half2*)&u);
            acc.x += v.x;
            acc.y += v.y;
        }
        j += m;
    }
    float sc = __ldg(&dis[w]);
    float2 bb = *(const float2*)(bias + lane * 2);
    *(float2*)(out + (size_t)w * 64 + lane * 2) =
        make_float2(fmaf(sc, acc.x, bb.x), fmaf(sc, acc.y, bb.y));
}

// ---------------------------- Launch ----------------------------------------

extern "C" void kernel_launch(void* const* d_in, const int* in_sizes, int n_in,
                              void* d_out, int out_size) {
    const int*   types = (const int*)d_in[0];
    const int*   ei    = (const int*)d_in[1];
    const float* emb   = (const float*)d_in[2];
    const float* W1    = (const float*)d_in[3];
    const float* b1    = (const float*)d_in[4];
    const float* W2    = (const float*)d_in[5];
    const float* b2    = (const float*)d_in[6];
    float* out = (float*)d_out;

    int n  = in_sizes[0];
    int e  = in_sizes[1] / 2;
    int nt = in_sizes[2] / 128;
    if (n > MAXN) n = MAXN;
    if (e > MAXE) e = MAXE;
    if (nt > MAXT) nt = MAXT;
    const int* src = ei;
    const int* dst = ei + e;

    int *cnt, *rowptr, *erank, *partials, *npay;
    int2 *ecsr;
    float *dis;
    __half *ht, *a1s, *h2;
    cudaGetSymbolAddress((void**)&cnt,      g_cnt);
    cudaGetSymbolAddress((void**)&rowptr,   g_rowptr);
    cudaGetSymbolAddress((void**)&erank,    g_erank);
    cudaGetSymbolAddress((void**)&ecsr,     g_ecsr);
    cudaGetSymbolAddress((void**)&partials, g_partials);
    cudaGetSymbolAddress((void**)&npay,     g_npay);
    cudaGetSymbolAddress((void**)&dis,      g_dis);
    cudaGetSymbolAddress((void**)&ht,       g_ht);
    cudaGetSymbolAddress((void**)&a1s,      g_a1s);
    cudaGetSymbolAddress((void**)&h2,       g_h2);

    int nb          = (n + SCAN_CHUNK - 1) / SCAN_CHUNK;
    int count_blocks = (e / 2 + 256) / 256;
    int gemm_blocks  = (nt + 63) / 64;

    cudaMemsetAsync(cnt, 0, (size_t)n * sizeof(int));

    // kernel 1: fused edge-count + type-GEMM (heterogeneous grid)
    count_gemmtype_kernel<<<count_blocks + gemm_blocks, 256>>>(
        dst, e, cnt, erank, partials, nb, emb, W1, ht, nt, count_blocks);
    // kernel 2: scan
    scan_fused_kernel<<<nb, 256>>>(cnt, types, partials, rowptr, dis, npay, n, nb);
    // kernel 3: fill
    fill_kernel<<<count_blocks, 256>>>(src, dst, rowptr, erank, npay, e, ecsr);

    int agg_blocks = (n + 7) / 8;

    // kernel 4: agg1 (ncu capture slot)
    agg1_fused_kernel<<<agg_blocks, 256>>>(ht, types, rowptr, ecsr, dis, b1, a1s, n);

    gemm2_tc_kernel<<<(n + 63) / 64, 256>>>(a1s, W2, h2, n);
    agg2_kernel<<<agg_blocks, 256>>>(h2, rowptr, ecsr, dis, b2, out, n);
}